// round 1
// baseline (speedup 1.0000x reference)
#include <cuda_runtime.h>

#define Nn 8192
#define Dd 256
#define BI 64
#define BJ 128
#define BK 32
#define ASTR 68
#define BSTR 132

__device__ float g_sqn[Nn];
__device__ int   g_hp[Nn];
__device__ int   g_hn[Nn];
__device__ float g_per[Nn];
__device__ int   g_val[Nn];

// ---------------- squared norms: one warp per row ----------------
__global__ void sqnorm_k(const float* __restrict__ emb) {
    int gw   = (blockIdx.x * blockDim.x + threadIdx.x) >> 5;
    int lane = threadIdx.x & 31;
    if (gw >= Nn) return;
    const float4* p = (const float4*)(emb + (size_t)gw * Dd);
    float s = 0.f;
    #pragma unroll
    for (int q = 0; q < 2; q++) {
        float4 v = p[lane + q * 32];
        s += v.x * v.x + v.y * v.y + v.z * v.z + v.w * v.w;
    }
    #pragma unroll
    for (int o = 16; o; o >>= 1) s += __shfl_xor_sync(0xffffffffu, s, o);
    if (!lane) g_sqn[gw] = s;
}

// ---------------- fused distance GEMM + hardest pos/neg mining ----------------
__global__ __launch_bounds__(256, 1)
void mine_k(const float* __restrict__ emb, const int* __restrict__ labels,
            const int* __restrict__ sbj) {
    __shared__ float a_t[BK][ASTR];   // a_t[k][row]
    __shared__ float b_t[BK][BSTR];   // b_t[k][col]
    __shared__ int   lab_s[BJ];
    __shared__ int   sbj_s[BJ];
    __shared__ float sqj_s[BJ];

    const int tid = threadIdx.x;
    const int tx  = tid & 15;
    const int ty  = tid >> 4;
    const int bi  = blockIdx.x * BI;

    float sqi[4]; int labi[4], sbji[4];
    #pragma unroll
    for (int r = 0; r < 4; r++) {
        int i = bi + ty * 4 + r;
        sqi[r]  = g_sqn[i];
        labi[r] = labels[i];
        sbji[r] = sbj[i];
    }

    float bpd[4], bnd[4]; int bpi[4], bni[4];
    #pragma unroll
    for (int r = 0; r < 4; r++) { bpd[r] = -1.f; bpi[r] = -1; bnd[r] = 3.4e38f; bni[r] = -1; }

    const int kq   = (tid & 7) * 4;   // k offset for loading
    const int lrow = tid >> 3;        // 0..31

    for (int jt = 0; jt < Nn; jt += BJ) {
        __syncthreads();   // protect prev epilogue reads of lab_s/sbj_s/sqj_s
        if (tid < BJ) {
            lab_s[tid] = labels[jt + tid];
            sbj_s[tid] = sbj[jt + tid];
            sqj_s[tid] = g_sqn[jt + tid];
        }

        float acc[4][8];
        #pragma unroll
        for (int r = 0; r < 4; r++)
            #pragma unroll
            for (int c = 0; c < 8; c++) acc[r][c] = 0.f;

        for (int kk = 0; kk < Dd; kk += BK) {
            // A tile: 64 rows x 32 k, transposed store
            #pragma unroll
            for (int p = 0; p < 2; p++) {
                int rr = lrow + p * 32;
                float4 v = *(const float4*)&emb[(size_t)(bi + rr) * Dd + kk + kq];
                a_t[kq + 0][rr] = v.x; a_t[kq + 1][rr] = v.y;
                a_t[kq + 2][rr] = v.z; a_t[kq + 3][rr] = v.w;
            }
            // B tile: 128 cols x 32 k, transposed store
            #pragma unroll
            for (int p = 0; p < 4; p++) {
                int cc = lrow + p * 32;
                float4 v = *(const float4*)&emb[(size_t)(jt + cc) * Dd + kk + kq];
                b_t[kq + 0][cc] = v.x; b_t[kq + 1][cc] = v.y;
                b_t[kq + 2][cc] = v.z; b_t[kq + 3][cc] = v.w;
            }
            __syncthreads();
            #pragma unroll
            for (int k = 0; k < BK; k++) {
                float4 a  = *(const float4*)&a_t[k][ty * 4];
                float4 b0 = *(const float4*)&b_t[k][tx * 8];
                float4 b1 = *(const float4*)&b_t[k][tx * 8 + 4];
                float av[4] = {a.x, a.y, a.z, a.w};
                float bv[8] = {b0.x, b0.y, b0.z, b0.w, b1.x, b1.y, b1.z, b1.w};
                #pragma unroll
                for (int r = 0; r < 4; r++)
                    #pragma unroll
                    for (int c = 0; c < 8; c++)
                        acc[r][c] = fmaf(av[r], bv[c], acc[r][c]);
            }
            __syncthreads();
        }

        // epilogue: masked hardest-pos / hardest-neg update on d^2
        #pragma unroll
        for (int c = 0; c < 8; c++) {
            int col = tx * 8 + c;
            int j   = jt + col;
            int lj  = lab_s[col];
            int sj  = sbj_s[col];
            float sqjv = sqj_s[col];
            #pragma unroll
            for (int r = 0; r < 4; r++) {
                if (sj == sbji[r]) {
                    float d2 = fmaxf(sqi[r] + sqjv - 2.f * acc[r][c], 0.f);
                    int i = bi + ty * 4 + r;
                    if (lj == labi[r]) {
                        if (j != i && d2 > bpd[r]) { bpd[r] = d2; bpi[r] = j; }
                    } else {
                        if (d2 < bnd[r]) { bnd[r] = d2; bni[r] = j; }
                    }
                }
            }
        }
    }

    // cross-tx reduction (16 lanes share the same 4 rows); min-index on ties
    #pragma unroll
    for (int r = 0; r < 4; r++) {
        float d = bpd[r]; int idx = bpi[r];
        #pragma unroll
        for (int off = 8; off; off >>= 1) {
            float od = __shfl_xor_sync(0xffffffffu, d, off);
            int   oi = __shfl_xor_sync(0xffffffffu, idx, off);
            if (oi >= 0 && (idx < 0 || od > d || (od == d && oi < idx))) { d = od; idx = oi; }
        }
        if (tx == 0) g_hp[bi + ty * 4 + r] = idx;

        float dn = bnd[r]; int idxn = bni[r];
        #pragma unroll
        for (int off = 8; off; off >>= 1) {
            float od = __shfl_xor_sync(0xffffffffu, dn, off);
            int   oi = __shfl_xor_sync(0xffffffffu, idxn, off);
            if (oi >= 0 && (idxn < 0 || od < dn || (od == dn && oi < idxn))) { dn = od; idxn = oi; }
        }
        if (tx == 0) g_hn[bi + ty * 4 + r] = idxn;
    }
}

// ---------------- per-row triplet loss (recomputed with +EPS) ----------------
__global__ void loss_k(const float* __restrict__ emb) {
    int gw   = (blockIdx.x * blockDim.x + threadIdx.x) >> 5;
    int lane = threadIdx.x & 31;
    if (gw >= Nn) return;
    int p = g_hp[gw], q = g_hn[gw];
    bool valid = (p >= 0) && (q >= 0);   // uniform per warp
    float per = 0.f;
    if (valid) {
        const float4* ei = (const float4*)(emb + (size_t)gw * Dd);
        const float4* ep = (const float4*)(emb + (size_t)p  * Dd);
        const float4* en = (const float4*)(emb + (size_t)q  * Dd);
        float sp = 0.f, sn = 0.f;
        const float eps = 1e-6f;
        #pragma unroll
        for (int t = 0; t < 2; t++) {
            float4 a = ei[lane + t * 32], b = ep[lane + t * 32], c = en[lane + t * 32];
            float d;
            d = a.x - b.x + eps; sp += d * d;
            d = a.y - b.y + eps; sp += d * d;
            d = a.z - b.z + eps; sp += d * d;
            d = a.w - b.w + eps; sp += d * d;
            d = a.x - c.x + eps; sn += d * d;
            d = a.y - c.y + eps; sn += d * d;
            d = a.z - c.z + eps; sn += d * d;
            d = a.w - c.w + eps; sn += d * d;
        }
        #pragma unroll
        for (int o = 16; o; o >>= 1) {
            sp += __shfl_xor_sync(0xffffffffu, sp, o);
            sn += __shfl_xor_sync(0xffffffffu, sn, o);
        }
        per = fmaxf(sqrtf(sp) - sqrtf(sn) + 1.0f, 0.f);
    }
    if (!lane) { g_per[gw] = per; g_val[gw] = valid ? 1 : 0; }
}

// ---------------- final scalar reduction ----------------
__global__ void reduce_k(float* __restrict__ out) {
    __shared__ double ss[256];
    __shared__ int    sc[256];
    int tid = threadIdx.x;
    double s = 0.0; int c = 0;
    for (int i = tid; i < Nn; i += 256) { s += (double)g_per[i]; c += g_val[i]; }
    ss[tid] = s; sc[tid] = c;
    __syncthreads();
    for (int o = 128; o; o >>= 1) {
        if (tid < o) { ss[tid] += ss[tid + o]; sc[tid] += sc[tid + o]; }
        __syncthreads();
    }
    if (!tid) {
        int cnt = sc[0] > 1 ? sc[0] : 1;
        out[0] = (float)(ss[0] / (double)cnt);
    }
}

extern "C" void kernel_launch(void* const* d_in, const int* in_sizes, int n_in,
                              void* d_out, int out_size) {
    const float* emb    = (const float*)d_in[0];
    const int*   labels = (const int*)d_in[1];
    const int*   sbjv   = (const int*)d_in[2];
    float* out = (float*)d_out;

    sqnorm_k<<<Nn / 8, 256>>>(emb);
    mine_k<<<Nn / BI, 256>>>(emb, labels, sbjv);
    loss_k<<<Nn / 8, 256>>>(emb);
    reduce_k<<<1, 256>>>(out);
}

// round 3
// speedup vs baseline: 2.2530x; 2.2530x over previous
#include <cuda_runtime.h>
#include <cstdint>

#define Nn 8192
#define Dd 256
#define TM 128
#define TN 128
#define NCH 8                 // K chunks of 32 floats

#define TILE_B   18432        // 128 rows * 36 floats * 4B
#define A_H      0
#define A_L      18432
#define B_H      36864
#define B_L      55296
#define STG      73728        // bytes per pipeline stage
#define META     147456       // meta arrays after the 2 stages
#define SMEM_DYN (META + 6*128*4)

__device__ __align__(256) float g_hi[Nn*Dd];
__device__ __align__(256) float g_lo[Nn*Dd];
__device__ float g_sqn[Nn];
__device__ unsigned long long g_bp[Nn];
__device__ unsigned long long g_bn[Nn];
__device__ float g_per[Nn];
__device__ int   g_val[Nn];

// ---------------- PTX helpers ----------------
__device__ __forceinline__ uint32_t smem_u32(const void* p) {
    uint32_t a;
    asm("{ .reg .u64 t; cvta.to.shared.u64 t, %1; cvt.u32.u64 %0, t; }" : "=r"(a) : "l"(p));
    return a;
}
__device__ __forceinline__ void cpa16(uint32_t dst, const float* src) {
    asm volatile("cp.async.cg.shared.global [%0], [%1], 16;" :: "r"(dst), "l"(src));
}
__device__ __forceinline__ void cpa_commit() { asm volatile("cp.async.commit_group;" ::: "memory"); }
__device__ __forceinline__ void cpa_wait1()  { asm volatile("cp.async.wait_group 1;" ::: "memory"); }
__device__ __forceinline__ void cpa_wait0()  { asm volatile("cp.async.wait_group 0;" ::: "memory"); }

__device__ __forceinline__ void mma8(float* c, const uint32_t* a, const uint32_t* b) {
    asm volatile("mma.sync.aligned.m16n8k8.row.col.f32.tf32.tf32.f32 "
        "{%0,%1,%2,%3}, {%4,%5,%6,%7}, {%8,%9}, {%0,%1,%2,%3};"
        : "+f"(c[0]), "+f"(c[1]), "+f"(c[2]), "+f"(c[3])
        : "r"(a[0]), "r"(a[1]), "r"(a[2]), "r"(a[3]), "r"(b[0]), "r"(b[1]));
}

// ---------------- prep: hi/lo split + sq norms + best-init ----------------
__global__ void prep_k(const float* __restrict__ emb) {
    int gw   = (blockIdx.x * blockDim.x + threadIdx.x) >> 5;
    int lane = threadIdx.x & 31;
    if (gw >= Nn) return;
    const float4* p = (const float4*)(emb + (size_t)gw * Dd);
    float4* ph = (float4*)(g_hi + (size_t)gw * Dd);
    float4* pl = (float4*)(g_lo + (size_t)gw * Dd);
    float s = 0.f;
    #pragma unroll
    for (int q = 0; q < 2; q++) {
        float4 v = p[lane + q * 32];
        float4 h, l;
        h.x = __uint_as_float(__float_as_uint(v.x) & 0xFFFFE000u); l.x = v.x - h.x;
        h.y = __uint_as_float(__float_as_uint(v.y) & 0xFFFFE000u); l.y = v.y - h.y;
        h.z = __uint_as_float(__float_as_uint(v.z) & 0xFFFFE000u); l.z = v.z - h.z;
        h.w = __uint_as_float(__float_as_uint(v.w) & 0xFFFFE000u); l.w = v.w - h.w;
        s += v.x * v.x + v.y * v.y + v.z * v.z + v.w * v.w;
        ph[lane + q * 32] = h;
        pl[lane + q * 32] = l;
    }
    #pragma unroll
    for (int o = 16; o; o >>= 1) s += __shfl_xor_sync(0xffffffffu, s, o);
    if (!lane) {
        g_sqn[gw] = s;
        g_bp[gw] = 0ull;
        g_bn[gw] = ~0ull;
    }
}

// ---------------- chunk loader: gmem -> padded row-major smem via cp.async ----------------
__device__ __forceinline__ void prefetch(uint32_t stg32, int i0, int j0, int kk, int tid) {
    #pragma unroll
    for (int t = 0; t < 16; t++) {
        int u    = tid + t * 256;          // 0..4095
        int tile = u >> 10;                // 0:Ah 1:Al 2:Bh 3:Bl
        int w    = u & 1023;
        int row  = w >> 3;                 // 0..127
        int k4   = w & 7;                  // 0..7
        uint32_t dst = stg32 + tile * TILE_B + row * 144 + k4 * 16;
        int base = (tile < 2 ? i0 : j0) + row;
        const float* g = (tile & 1) ? g_lo : g_hi;
        cpa16(dst, g + (size_t)base * Dd + kk + k4 * 4);
    }
}

// ---------------- fused 3xTF32 distance GEMM (mma.sync) + hardest mining ----------------
__global__ __launch_bounds__(256, 1)
void mine_k(const int* __restrict__ labels, const int* __restrict__ sbj) {
    extern __shared__ __align__(16) char sb[];
    const uint32_t sb32 = smem_u32(sb);

    const int tid  = threadIdx.x;
    const int wid  = tid >> 5;
    const int lane = tid & 31;
    const int gr   = lane >> 2;     // 0..7
    const int gc   = lane & 3;      // 0..3
    const int wy   = wid >> 2;      // 0..1  (M)
    const int wx   = wid & 3;       // 0..3  (N)

    const int i0 = (blockIdx.x >> 6) * TM;
    const int j0 = (blockIdx.x & 63) * TN;

    int*   s_labi = (int*)  (sb + META);
    int*   s_sbji = (int*)  (sb + META + 512);
    float* s_sqi  = (float*)(sb + META + 1024);
    int*   s_labj = (int*)  (sb + META + 1536);
    int*   s_sbjj = (int*)  (sb + META + 2048);
    float* s_sqj  = (float*)(sb + META + 2560);

    if (tid < 128) {
        s_labi[tid] = labels[i0 + tid];
        s_sbji[tid] = sbj[i0 + tid];
        s_sqi[tid]  = g_sqn[i0 + tid];
        s_labj[tid] = labels[j0 + tid];
        s_sbjj[tid] = sbj[j0 + tid];
        s_sqj[tid]  = g_sqn[j0 + tid];
    }

    prefetch(sb32,       i0, j0,  0, tid); cpa_commit();
    prefetch(sb32 + STG, i0, j0, 32, tid); cpa_commit();

    float acc[4][4][4];
    #pragma unroll
    for (int mt = 0; mt < 4; mt++)
        #pragma unroll
        for (int nt = 0; nt < 4; nt++)
            #pragma unroll
            for (int q = 0; q < 4; q++) acc[mt][nt][q] = 0.f;

    for (int c = 0; c < NCH; c++) {
        const int st = c & 1;
        if (c < NCH - 1) cpa_wait1(); else cpa_wait0();
        __syncthreads();

        const float* sa_h = (const float*)(sb + st * STG + A_H);
        const float* sa_l = (const float*)(sb + st * STG + A_L);
        const float* sb_h = (const float*)(sb + st * STG + B_H);
        const float* sb_l = (const float*)(sb + st * STG + B_L);

        #pragma unroll
        for (int kc = 0; kc < 32; kc += 8) {
            uint32_t ah[4][4], al[4][4], bh[4][2], bl[4][2];
            #pragma unroll
            for (int mt = 0; mt < 4; mt++) {
                int off = (wy * 64 + mt * 16 + gr) * 36 + kc + gc;
                ah[mt][0] = __float_as_uint(sa_h[off]);
                ah[mt][1] = __float_as_uint(sa_h[off + 288]);
                ah[mt][2] = __float_as_uint(sa_h[off + 4]);
                ah[mt][3] = __float_as_uint(sa_h[off + 292]);
                al[mt][0] = __float_as_uint(sa_l[off]);
                al[mt][1] = __float_as_uint(sa_l[off + 288]);
                al[mt][2] = __float_as_uint(sa_l[off + 4]);
                al[mt][3] = __float_as_uint(sa_l[off + 292]);
            }
            #pragma unroll
            for (int nt = 0; nt < 4; nt++) {
                int off = (wx * 32 + nt * 8 + gr) * 36 + kc + gc;
                bh[nt][0] = __float_as_uint(sb_h[off]);
                bh[nt][1] = __float_as_uint(sb_h[off + 4]);
                bl[nt][0] = __float_as_uint(sb_l[off]);
                bl[nt][1] = __float_as_uint(sb_l[off + 4]);
            }
            #pragma unroll
            for (int mt = 0; mt < 4; mt++)
                #pragma unroll
                for (int nt = 0; nt < 4; nt++) {
                    mma8(acc[mt][nt], ah[mt], bh[nt]);
                    mma8(acc[mt][nt], ah[mt], bl[nt]);
                    mma8(acc[mt][nt], al[mt], bh[nt]);
                }
        }
        __syncthreads();
        if (c + 2 < NCH) {
            prefetch(sb32 + st * STG, i0, j0, (c + 2) * 32, tid);
            cpa_commit();
        }
    }

    // ---------- epilogue: mine hardest positive / negative per row ----------
    float sqjv[8]; int labj[8], sbjj[8], jg[8];
    #pragma unroll
    for (int nt = 0; nt < 4; nt++)
        #pragma unroll
        for (int e = 0; e < 2; e++) {
            int q = nt * 2 + e;
            int cl = wx * 32 + nt * 8 + 2 * gc + e;
            sqjv[q] = s_sqj[cl]; labj[q] = s_labj[cl]; sbjj[q] = s_sbjj[cl];
            jg[q] = j0 + cl;
        }

    #pragma unroll
    for (int mt = 0; mt < 4; mt++)
        #pragma unroll
        for (int h = 0; h < 2; h++) {
            int rl = wy * 64 + mt * 16 + gr + h * 8;
            int ig = i0 + rl;
            float sqi = s_sqi[rl];
            int li = s_labi[rl], si = s_sbji[rl];
            float bpd = -1.f;    int bpi = -1;
            float bnd = 3.4e38f; int bni = -1;
            #pragma unroll
            for (int q = 0; q < 8; q++) {
                float d2 = fmaxf(fmaf(-2.f, acc[mt][q >> 1][h * 2 + (q & 1)], sqi + sqjv[q]), 0.f);
                if (sbjj[q] == si) {
                    if (labj[q] == li) {
                        if (jg[q] != ig && d2 > bpd) { bpd = d2; bpi = jg[q]; }
                    } else {
                        if (d2 < bnd) { bnd = d2; bni = jg[q]; }
                    }
                }
            }
            // merge across the 4 lanes (gc) holding this row
            #pragma unroll
            for (int o = 1; o < 4; o <<= 1) {
                float od = __shfl_xor_sync(0xffffffffu, bpd, o);
                int   oi = __shfl_xor_sync(0xffffffffu, bpi, o);
                if (oi >= 0 && (bpi < 0 || od > bpd || (od == bpd && oi < bpi))) { bpd = od; bpi = oi; }
                od = __shfl_xor_sync(0xffffffffu, bnd, o);
                oi = __shfl_xor_sync(0xffffffffu, bni, o);
                if (oi >= 0 && (bni < 0 || od < bnd || (od == bnd && oi < bni))) { bnd = od; bni = oi; }
            }
            if (gc == 0) {
                if (bpi >= 0)
                    atomicMax(&g_bp[ig], ((unsigned long long)__float_as_uint(bpd) << 32) |
                                         (unsigned long long)(~(unsigned)bpi));
                if (bni >= 0)
                    atomicMin(&g_bn[ig], ((unsigned long long)__float_as_uint(bnd) << 32) |
                                         (unsigned long long)(unsigned)bni);
            }
        }
}

// ---------------- per-row triplet loss (exact fp32 recompute with +EPS) ----------------
__global__ void loss_k(const float* __restrict__ emb) {
    int gw   = (blockIdx.x * blockDim.x + threadIdx.x) >> 5;
    int lane = threadIdx.x & 31;
    if (gw >= Nn) return;
    unsigned long long pp = g_bp[gw], pn = g_bn[gw];
    int p = (pp == 0ull)  ? -1 : (int)(~(unsigned)(pp & 0xFFFFFFFFull));
    int q = (pn == ~0ull) ? -1 : (int)(unsigned)(pn & 0xFFFFFFFFull);
    bool valid = (p >= 0) && (q >= 0);
    float per = 0.f;
    if (valid) {
        const float4* ei = (const float4*)(emb + (size_t)gw * Dd);
        const float4* ep = (const float4*)(emb + (size_t)p  * Dd);
        const float4* en = (const float4*)(emb + (size_t)q  * Dd);
        float sp = 0.f, sn = 0.f;
        const float eps = 1e-6f;
        #pragma unroll
        for (int t = 0; t < 2; t++) {
            float4 a = ei[lane + t * 32], b = ep[lane + t * 32], c = en[lane + t * 32];
            float d;
            d = a.x - b.x + eps; sp += d * d;
            d = a.y - b.y + eps; sp += d * d;
            d = a.z - b.z + eps; sp += d * d;
            d = a.w - b.w + eps; sp += d * d;
            d = a.x - c.x + eps; sn += d * d;
            d = a.y - c.y + eps; sn += d * d;
            d = a.z - c.z + eps; sn += d * d;
            d = a.w - c.w + eps; sn += d * d;
        }
        #pragma unroll
        for (int o = 16; o; o >>= 1) {
            sp += __shfl_xor_sync(0xffffffffu, sp, o);
            sn += __shfl_xor_sync(0xffffffffu, sn, o);
        }
        per = fmaxf(sqrtf(sp) - sqrtf(sn) + 1.0f, 0.f);
    }
    if (!lane) { g_per[gw] = per; g_val[gw] = valid ? 1 : 0; }
}

// ---------------- final scalar reduction ----------------
__global__ void reduce_k(float* __restrict__ out) {
    __shared__ double ss[256];
    __shared__ int    sc[256];
    int tid = threadIdx.x;
    double s = 0.0; int c = 0;
    for (int i = tid; i < Nn; i += 256) { s += (double)g_per[i]; c += g_val[i]; }
    ss[tid] = s; sc[tid] = c;
    __syncthreads();
    for (int o = 128; o; o >>= 1) {
        if (tid < o) { ss[tid] += ss[tid + o]; sc[tid] += sc[tid + o]; }
        __syncthreads();
    }
    if (!tid) {
        int cnt = sc[0] > 1 ? sc[0] : 1;
        out[0] = (float)(ss[0] / (double)cnt);
    }
}

extern "C" void kernel_launch(void* const* d_in, const int* in_sizes, int n_in,
                              void* d_out, int out_size) {
    const float* emb    = (const float*)d_in[0];
    const int*   labels = (const int*)d_in[1];
    const int*   sbjv   = (const int*)d_in[2];
    float* out = (float*)d_out;

    cudaFuncSetAttribute(mine_k, cudaFuncAttributeMaxDynamicSharedMemorySize, SMEM_DYN);

    prep_k<<<Nn / 8, 256>>>(emb);
    mine_k<<<(Nn / TM) * (Nn / TN), 256, SMEM_DYN>>>(labels, sbjv);
    loss_k<<<Nn / 8, 256>>>(emb);
    reduce_k<<<1, 256>>>(out);
}

// round 4
// speedup vs baseline: 4.6375x; 2.0584x over previous
#include <cuda_runtime.h>
#include <cuda_bf16.h>
#include <cstdint>

#define Nn 8192
#define Dd 256
#define TM 128
#define TN 128
#define NCH 8                 // K chunks of 32 elements

#define RS     40             // smem row stride in bf16 elems (80B, conflict-free)
#define TILE_B 10240          // 128 rows * 80B
#define A_H    0
#define A_L    10240
#define B_H    20480
#define B_L    30720
#define STG    40960          // bytes per pipeline stage
#define META   81920
#define SMEM_DYN (META + 6*128*4)

__device__ __align__(256) __nv_bfloat16 g_hi[Nn*Dd];
__device__ __align__(256) __nv_bfloat16 g_lo[Nn*Dd];
__device__ float g_sqn[Nn];
__device__ unsigned long long g_bp[Nn];
__device__ unsigned long long g_bn[Nn];
__device__ float g_per[Nn];
__device__ int   g_val[Nn];

// ---------------- PTX helpers ----------------
__device__ __forceinline__ uint32_t smem_u32(const void* p) {
    uint32_t a;
    asm("{ .reg .u64 t; cvta.to.shared.u64 t, %1; cvt.u32.u64 %0, t; }" : "=r"(a) : "l"(p));
    return a;
}
__device__ __forceinline__ void cpa16(uint32_t dst, const __nv_bfloat16* src) {
    asm volatile("cp.async.cg.shared.global [%0], [%1], 16;" :: "r"(dst), "l"(src));
}
__device__ __forceinline__ void cpa_commit() { asm volatile("cp.async.commit_group;" ::: "memory"); }
__device__ __forceinline__ void cpa_wait1()  { asm volatile("cp.async.wait_group 1;" ::: "memory"); }
__device__ __forceinline__ void cpa_wait0()  { asm volatile("cp.async.wait_group 0;" ::: "memory"); }

__device__ __forceinline__ void mma16(float* c, const uint32_t* a, const uint32_t* b) {
    asm volatile("mma.sync.aligned.m16n8k16.row.col.f32.bf16.bf16.f32 "
        "{%0,%1,%2,%3}, {%4,%5,%6,%7}, {%8,%9}, {%0,%1,%2,%3};"
        : "+f"(c[0]), "+f"(c[1]), "+f"(c[2]), "+f"(c[3])
        : "r"(a[0]), "r"(a[1]), "r"(a[2]), "r"(a[3]), "r"(b[0]), "r"(b[1]));
}

// ---------------- prep: bf16 hi/lo split + sq norms + best-init ----------------
__global__ void prep_k(const float* __restrict__ emb) {
    int gw   = (blockIdx.x * blockDim.x + threadIdx.x) >> 5;
    int lane = threadIdx.x & 31;
    if (gw >= Nn) return;
    const float4* p = (const float4*)(emb + (size_t)gw * Dd);
    __nv_bfloat162* ph = (__nv_bfloat162*)(g_hi + (size_t)gw * Dd);
    __nv_bfloat162* pl = (__nv_bfloat162*)(g_lo + (size_t)gw * Dd);
    float s = 0.f;
    #pragma unroll
    for (int q = 0; q < 2; q++) {
        int e = lane + q * 32;
        float4 v = p[e];
        __nv_bfloat16 hx = __float2bfloat16_rn(v.x), hy = __float2bfloat16_rn(v.y);
        __nv_bfloat16 hz = __float2bfloat16_rn(v.z), hw = __float2bfloat16_rn(v.w);
        __nv_bfloat16 lx = __float2bfloat16_rn(v.x - __bfloat162float(hx));
        __nv_bfloat16 ly = __float2bfloat16_rn(v.y - __bfloat162float(hy));
        __nv_bfloat16 lz = __float2bfloat16_rn(v.z - __bfloat162float(hz));
        __nv_bfloat16 lw = __float2bfloat16_rn(v.w - __bfloat162float(hw));
        ph[2*e]   = __nv_bfloat162(hx, hy);
        ph[2*e+1] = __nv_bfloat162(hz, hw);
        pl[2*e]   = __nv_bfloat162(lx, ly);
        pl[2*e+1] = __nv_bfloat162(lz, lw);
        s += v.x * v.x + v.y * v.y + v.z * v.z + v.w * v.w;
    }
    #pragma unroll
    for (int o = 16; o; o >>= 1) s += __shfl_xor_sync(0xffffffffu, s, o);
    if (!lane) {
        g_sqn[gw] = s;
        g_bp[gw] = 0ull;
        g_bn[gw] = ~0ull;
    }
}

// ---------------- chunk loader: gmem -> padded row-major smem via cp.async ----------------
__device__ __forceinline__ void prefetch(uint32_t stg32, int i0, int j0, int kk, int tid) {
    #pragma unroll
    for (int t = 0; t < 8; t++) {
        int u    = tid + t * 256;          // 0..2047
        int tile = u >> 9;                 // 0:Ah 1:Al 2:Bh 3:Bl
        int w    = u & 511;
        int row  = w >> 2;                 // 0..127
        int k4   = w & 3;                  // 0..3 (16B = 8 bf16 each)
        uint32_t dst = stg32 + tile * TILE_B + row * (RS * 2) + k4 * 16;
        int base = (tile < 2 ? i0 : j0) + row;
        const __nv_bfloat16* g = (tile & 1) ? g_lo : g_hi;
        cpa16(dst, g + (size_t)base * Dd + kk + k4 * 8);
    }
}

// ---------------- fused 3xbf16 distance GEMM (mma.sync) + hardest mining ----------------
__global__ __launch_bounds__(256, 2)
void mine_k(const int* __restrict__ labels, const int* __restrict__ sbj) {
    extern __shared__ __align__(16) char sb[];
    const uint32_t sb32 = smem_u32(sb);

    const int tid  = threadIdx.x;
    const int wid  = tid >> 5;
    const int lane = tid & 31;
    const int gr   = lane >> 2;     // 0..7
    const int gc   = lane & 3;      // 0..3
    const int wy   = wid >> 2;      // 0..1  (M)
    const int wx   = wid & 3;       // 0..3  (N)

    const int i0 = (blockIdx.x >> 6) * TM;
    const int j0 = (blockIdx.x & 63) * TN;

    int*   s_labi = (int*)  (sb + META);
    int*   s_sbji = (int*)  (sb + META + 512);
    float* s_sqi  = (float*)(sb + META + 1024);
    int*   s_labj = (int*)  (sb + META + 1536);
    int*   s_sbjj = (int*)  (sb + META + 2048);
    float* s_sqj  = (float*)(sb + META + 2560);

    if (tid < 128) {
        s_labi[tid] = labels[i0 + tid];
        s_sbji[tid] = sbj[i0 + tid];
        s_sqi[tid]  = g_sqn[i0 + tid];
        s_labj[tid] = labels[j0 + tid];
        s_sbjj[tid] = sbj[j0 + tid];
        s_sqj[tid]  = g_sqn[j0 + tid];
    }

    prefetch(sb32,       i0, j0,  0, tid); cpa_commit();
    prefetch(sb32 + STG, i0, j0, 32, tid); cpa_commit();

    float acc[4][4][4];
    #pragma unroll
    for (int mt = 0; mt < 4; mt++)
        #pragma unroll
        for (int nt = 0; nt < 4; nt++)
            #pragma unroll
            for (int q = 0; q < 4; q++) acc[mt][nt][q] = 0.f;

    for (int c = 0; c < NCH; c++) {
        const int st = c & 1;
        if (c < NCH - 1) cpa_wait1(); else cpa_wait0();
        __syncthreads();

        const uint32_t* sa_h = (const uint32_t*)(sb + st * STG + A_H);
        const uint32_t* sa_l = (const uint32_t*)(sb + st * STG + A_L);
        const uint32_t* sb_h = (const uint32_t*)(sb + st * STG + B_H);
        const uint32_t* sb_l = (const uint32_t*)(sb + st * STG + B_L);

        #pragma unroll
        for (int kc = 0; kc < 32; kc += 16) {
            // B fragments first (kept live across mt loop)
            uint32_t bh[4][2], bl[4][2];
            #pragma unroll
            for (int nt = 0; nt < 4; nt++) {
                int off = ((wx * 32 + nt * 8 + gr) * RS + kc) / 2 + gc;  // u32 index
                bh[nt][0] = sb_h[off];     bh[nt][1] = sb_h[off + 4];
                bl[nt][0] = sb_l[off];     bl[nt][1] = sb_l[off + 4];
            }
            #pragma unroll
            for (int mt = 0; mt < 4; mt++) {
                uint32_t ah[4], al[4];
                int off = ((wy * 64 + mt * 16 + gr) * RS + kc) / 2 + gc;
                ah[0] = sa_h[off];                ah[1] = sa_h[off + 4 * RS];
                ah[2] = sa_h[off + 4];            ah[3] = sa_h[off + 4 * RS + 4];
                al[0] = sa_l[off];                al[1] = sa_l[off + 4 * RS];
                al[2] = sa_l[off + 4];            al[3] = sa_l[off + 4 * RS + 4];
                #pragma unroll
                for (int nt = 0; nt < 4; nt++) {
                    mma16(acc[mt][nt], ah, bh[nt]);
                    mma16(acc[mt][nt], ah, bl[nt]);
                    mma16(acc[mt][nt], al, bh[nt]);
                }
            }
        }
        __syncthreads();
        if (c + 2 < NCH) {
            prefetch(sb32 + st * STG, i0, j0, (c + 2) * 32, tid);
            cpa_commit();
        }
    }

    // ---------- epilogue: mine hardest positive / negative per row ----------
    float sqjv[8]; int labj[8], sbjj[8], jg[8];
    #pragma unroll
    for (int nt = 0; nt < 4; nt++)
        #pragma unroll
        for (int e = 0; e < 2; e++) {
            int q = nt * 2 + e;
            int cl = wx * 32 + nt * 8 + 2 * gc + e;
            sqjv[q] = s_sqj[cl]; labj[q] = s_labj[cl]; sbjj[q] = s_sbjj[cl];
            jg[q] = j0 + cl;
        }

    #pragma unroll
    for (int mt = 0; mt < 4; mt++)
        #pragma unroll
        for (int h = 0; h < 2; h++) {
            int rl = wy * 64 + mt * 16 + gr + h * 8;
            int ig = i0 + rl;
            float sqi = s_sqi[rl];
            int li = s_labi[rl], si = s_sbji[rl];
            float bpd = -1.f;    int bpi = -1;
            float bnd = 3.4e38f; int bni = -1;
            #pragma unroll
            for (int q = 0; q < 8; q++) {
                float d2 = fmaxf(fmaf(-2.f, acc[mt][q >> 1][h * 2 + (q & 1)], sqi + sqjv[q]), 0.f);
                if (sbjj[q] == si) {
                    if (labj[q] == li) {
                        if (jg[q] != ig && d2 > bpd) { bpd = d2; bpi = jg[q]; }
                    } else {
                        if (d2 < bnd) { bnd = d2; bni = jg[q]; }
                    }
                }
            }
            // merge across the 4 lanes (gc) holding this row
            #pragma unroll
            for (int o = 1; o < 4; o <<= 1) {
                float od = __shfl_xor_sync(0xffffffffu, bpd, o);
                int   oi = __shfl_xor_sync(0xffffffffu, bpi, o);
                if (oi >= 0 && (bpi < 0 || od > bpd || (od == bpd && oi < bpi))) { bpd = od; bpi = oi; }
                od = __shfl_xor_sync(0xffffffffu, bnd, o);
                oi = __shfl_xor_sync(0xffffffffu, bni, o);
                if (oi >= 0 && (bni < 0 || od < bnd || (od == bnd && oi < bni))) { bnd = od; bni = oi; }
            }
            if (gc == 0) {
                if (bpi >= 0)
                    atomicMax(&g_bp[ig], ((unsigned long long)__float_as_uint(bpd) << 32) |
                                         (unsigned long long)(~(unsigned)bpi));
                if (bni >= 0)
                    atomicMin(&g_bn[ig], ((unsigned long long)__float_as_uint(bnd) << 32) |
                                         (unsigned long long)(unsigned)bni);
            }
        }
}

// ---------------- per-row triplet loss (exact fp32 recompute with +EPS) ----------------
__global__ void loss_k(const float* __restrict__ emb) {
    int gw   = (blockIdx.x * blockDim.x + threadIdx.x) >> 5;
    int lane = threadIdx.x & 31;
    if (gw >= Nn) return;
    unsigned long long pp = g_bp[gw], pn = g_bn[gw];
    int p = (pp == 0ull)  ? -1 : (int)(~(unsigned)(pp & 0xFFFFFFFFull));
    int q = (pn == ~0ull) ? -1 : (int)(unsigned)(pn & 0xFFFFFFFFull);
    bool valid = (p >= 0) && (q >= 0);
    float per = 0.f;
    if (valid) {
        const float4* ei = (const float4*)(emb + (size_t)gw * Dd);
        const float4* ep = (const float4*)(emb + (size_t)p  * Dd);
        const float4* en = (const float4*)(emb + (size_t)q  * Dd);
        float sp = 0.f, sn = 0.f;
        const float eps = 1e-6f;
        #pragma unroll
        for (int t = 0; t < 2; t++) {
            float4 a = ei[lane + t * 32], b = ep[lane + t * 32], c = en[lane + t * 32];
            float d;
            d = a.x - b.x + eps; sp += d * d;
            d = a.y - b.y + eps; sp += d * d;
            d = a.z - b.z + eps; sp += d * d;
            d = a.w - b.w + eps; sp += d * d;
            d = a.x - c.x + eps; sn += d * d;
            d = a.y - c.y + eps; sn += d * d;
            d = a.z - c.z + eps; sn += d * d;
            d = a.w - c.w + eps; sn += d * d;
        }
        #pragma unroll
        for (int o = 16; o; o >>= 1) {
            sp += __shfl_xor_sync(0xffffffffu, sp, o);
            sn += __shfl_xor_sync(0xffffffffu, sn, o);
        }
        per = fmaxf(sqrtf(sp) - sqrtf(sn) + 1.0f, 0.f);
    }
    if (!lane) { g_per[gw] = per; g_val[gw] = valid ? 1 : 0; }
}

// ---------------- final scalar reduction ----------------
__global__ void reduce_k(float* __restrict__ out) {
    __shared__ double ss[256];
    __shared__ int    sc[256];
    int tid = threadIdx.x;
    double s = 0.0; int c = 0;
    for (int i = tid; i < Nn; i += 256) { s += (double)g_per[i]; c += g_val[i]; }
    ss[tid] = s; sc[tid] = c;
    __syncthreads();
    for (int o = 128; o; o >>= 1) {
        if (tid < o) { ss[tid] += ss[tid + o]; sc[tid] += sc[tid + o]; }
        __syncthreads();
    }
    if (!tid) {
        int cnt = sc[0] > 1 ? sc[0] : 1;
        out[0] = (float)(ss[0] / (double)cnt);
    }
}

extern "C" void kernel_launch(void* const* d_in, const int* in_sizes, int n_in,
                              void* d_out, int out_size) {
    const float* emb    = (const float*)d_in[0];
    const int*   labels = (const int*)d_in[1];
    const int*   sbjv   = (const int*)d_in[2];
    float* out = (float*)d_out;

    cudaFuncSetAttribute(mine_k, cudaFuncAttributeMaxDynamicSharedMemorySize, SMEM_DYN);

    prep_k<<<Nn / 8, 256>>>(emb);
    mine_k<<<(Nn / TM) * (Nn / TN), 256, SMEM_DYN>>>(labels, sbjv);
    loss_k<<<Nn / 8, 256>>>(emb);
    reduce_k<<<1, 256>>>(out);
}

// round 5
// speedup vs baseline: 6.0809x; 1.3112x over previous
#include <cuda_runtime.h>
#include <cuda_bf16.h>
#include <cstdint>
#include <math.h>

#define Nn 8192
#define Dd 256
#define TM 128
#define TN 128
#define NT 64                 // tiles per dimension
#define NTRI (NT*(NT+1)/2)    // 2080 upper-tri tiles
#define NCH 8                 // K chunks of 32 elements

#define RS     40             // smem row stride in bf16 elems (80B, conflict-free)
#define TILE_B 10240          // 128 rows * 80B
#define A_H    0
#define A_L    10240
#define B_H    20480
#define B_L    30720
#define STG    40960          // bytes per pipeline stage
#define META   81920
#define SMEM_DYN (META + 6*128*4)

__device__ __align__(256) __nv_bfloat16 g_hi[Nn*Dd];
__device__ __align__(256) __nv_bfloat16 g_lo[Nn*Dd];
__device__ float g_sqn[Nn];
__device__ unsigned long long g_bp[Nn];
__device__ unsigned long long g_bn[Nn];
__device__ float g_per[Nn];
__device__ int   g_val[Nn];

// ---------------- PTX helpers ----------------
__device__ __forceinline__ uint32_t smem_u32(const void* p) {
    uint32_t a;
    asm("{ .reg .u64 t; cvta.to.shared.u64 t, %1; cvt.u32.u64 %0, t; }" : "=r"(a) : "l"(p));
    return a;
}
__device__ __forceinline__ void cpa16(uint32_t dst, const __nv_bfloat16* src) {
    asm volatile("cp.async.cg.shared.global [%0], [%1], 16;" :: "r"(dst), "l"(src));
}
__device__ __forceinline__ void cpa_commit() { asm volatile("cp.async.commit_group;" ::: "memory"); }
__device__ __forceinline__ void cpa_wait1()  { asm volatile("cp.async.wait_group 1;" ::: "memory"); }
__device__ __forceinline__ void cpa_wait0()  { asm volatile("cp.async.wait_group 0;" ::: "memory"); }

__device__ __forceinline__ void mma16(float* c, const uint32_t* a, const uint32_t* b) {
    asm volatile("mma.sync.aligned.m16n8k16.row.col.f32.bf16.bf16.f32 "
        "{%0,%1,%2,%3}, {%4,%5,%6,%7}, {%8,%9}, {%0,%1,%2,%3};"
        : "+f"(c[0]), "+f"(c[1]), "+f"(c[2]), "+f"(c[3])
        : "r"(a[0]), "r"(a[1]), "r"(a[2]), "r"(a[3]), "r"(b[0]), "r"(b[1]));
}

// ---------------- prep: bf16 hi/lo split + sq norms + best-init ----------------
__global__ void prep_k(const float* __restrict__ emb) {
    int gw   = (blockIdx.x * blockDim.x + threadIdx.x) >> 5;
    int lane = threadIdx.x & 31;
    if (gw >= Nn) return;
    const float4* p = (const float4*)(emb + (size_t)gw * Dd);
    __nv_bfloat162* ph = (__nv_bfloat162*)(g_hi + (size_t)gw * Dd);
    __nv_bfloat162* pl = (__nv_bfloat162*)(g_lo + (size_t)gw * Dd);
    float s = 0.f;
    #pragma unroll
    for (int q = 0; q < 2; q++) {
        int e = lane + q * 32;
        float4 v = p[e];
        __nv_bfloat16 hx = __float2bfloat16_rn(v.x), hy = __float2bfloat16_rn(v.y);
        __nv_bfloat16 hz = __float2bfloat16_rn(v.z), hw = __float2bfloat16_rn(v.w);
        __nv_bfloat16 lx = __float2bfloat16_rn(v.x - __bfloat162float(hx));
        __nv_bfloat16 ly = __float2bfloat16_rn(v.y - __bfloat162float(hy));
        __nv_bfloat16 lz = __float2bfloat16_rn(v.z - __bfloat162float(hz));
        __nv_bfloat16 lw = __float2bfloat16_rn(v.w - __bfloat162float(hw));
        ph[2*e]   = __nv_bfloat162(hx, hy);
        ph[2*e+1] = __nv_bfloat162(hz, hw);
        pl[2*e]   = __nv_bfloat162(lx, ly);
        pl[2*e+1] = __nv_bfloat162(lz, lw);
        s += v.x * v.x + v.y * v.y + v.z * v.z + v.w * v.w;
    }
    #pragma unroll
    for (int o = 16; o; o >>= 1) s += __shfl_xor_sync(0xffffffffu, s, o);
    if (!lane) {
        g_sqn[gw] = s;
        g_bp[gw] = 0ull;
        g_bn[gw] = ~0ull;
    }
}

// ---------------- chunk loader: gmem -> padded row-major smem via cp.async ----------------
__device__ __forceinline__ void prefetch(uint32_t stg32, int i0, int j0, int kk, int tid) {
    #pragma unroll
    for (int t = 0; t < 8; t++) {
        int u    = tid + t * 256;          // 0..2047
        int tile = u >> 9;                 // 0:Ah 1:Al 2:Bh 3:Bl
        int w    = u & 511;
        int row  = w >> 2;                 // 0..127
        int k4   = w & 3;                  // 0..3 (16B = 8 bf16 each)
        uint32_t dst = stg32 + tile * TILE_B + row * (RS * 2) + k4 * 16;
        int base = (tile < 2 ? i0 : j0) + row;
        const __nv_bfloat16* g = (tile & 1) ? g_lo : g_hi;
        cpa16(dst, g + (size_t)base * Dd + kk + k4 * 8);
    }
}

// ---------------- fused 3xbf16 distance GEMM + bidirectional hardest mining ----------------
__global__ __launch_bounds__(256, 2)
void mine_k(const int* __restrict__ labels, const int* __restrict__ sbj) {
    extern __shared__ __align__(16) char sb[];
    const uint32_t sb32 = smem_u32(sb);

    const int tid  = threadIdx.x;
    const int wid  = tid >> 5;
    const int lane = tid & 31;
    const int gr   = lane >> 2;     // 0..7
    const int gc   = lane & 3;      // 0..3
    const int wy   = wid >> 2;      // 0..1  (M)
    const int wx   = wid & 3;       // 0..3  (N)

    // decode triangular tile index: tiles (ta, tb), ta <= tb
    const int u = blockIdx.x;
    int ta = (int)((129.0 - sqrt(129.0 * 129.0 - 8.0 * (double)u)) * 0.5);
    while ((ta + 1) * NT - ((ta + 1) * ta) / 2 <= u) ta++;   // f(a)=a*NT - a(a-1)/2
    while (ta * NT - (ta * (ta - 1)) / 2 > u) ta--;
    const int tb = ta + (u - (ta * NT - (ta * (ta - 1)) / 2));
    const int i0 = ta * TM;
    const int j0 = tb * TN;
    const bool diag = (ta == tb);

    int*   s_labi = (int*)  (sb + META);
    int*   s_sbji = (int*)  (sb + META + 512);
    float* s_sqi  = (float*)(sb + META + 1024);
    int*   s_labj = (int*)  (sb + META + 1536);
    int*   s_sbjj = (int*)  (sb + META + 2048);
    float* s_sqj  = (float*)(sb + META + 2560);

    if (tid < 128) {
        s_labi[tid] = labels[i0 + tid];
        s_sbji[tid] = sbj[i0 + tid];
        s_sqi[tid]  = g_sqn[i0 + tid];
        s_labj[tid] = labels[j0 + tid];
        s_sbjj[tid] = sbj[j0 + tid];
        s_sqj[tid]  = g_sqn[j0 + tid];
    }

    prefetch(sb32,       i0, j0,  0, tid); cpa_commit();
    prefetch(sb32 + STG, i0, j0, 32, tid); cpa_commit();

    float acc[4][4][4];
    #pragma unroll
    for (int mt = 0; mt < 4; mt++)
        #pragma unroll
        for (int nt = 0; nt < 4; nt++)
            #pragma unroll
            for (int q = 0; q < 4; q++) acc[mt][nt][q] = 0.f;

    for (int c = 0; c < NCH; c++) {
        const int st = c & 1;
        if (c < NCH - 1) cpa_wait1(); else cpa_wait0();
        __syncthreads();

        const uint32_t* sa_h = (const uint32_t*)(sb + st * STG + A_H);
        const uint32_t* sa_l = (const uint32_t*)(sb + st * STG + A_L);
        const uint32_t* sb_h = (const uint32_t*)(sb + st * STG + B_H);
        const uint32_t* sb_l = (const uint32_t*)(sb + st * STG + B_L);

        #pragma unroll
        for (int kc = 0; kc < 32; kc += 16) {
            uint32_t bh[4][2], bl[4][2];
            #pragma unroll
            for (int nt = 0; nt < 4; nt++) {
                int off = ((wx * 32 + nt * 8 + gr) * RS + kc) / 2 + gc;
                bh[nt][0] = sb_h[off];     bh[nt][1] = sb_h[off + 4];
                bl[nt][0] = sb_l[off];     bl[nt][1] = sb_l[off + 4];
            }
            #pragma unroll
            for (int mt = 0; mt < 4; mt++) {
                uint32_t ah[4], al[4];
                int off = ((wy * 64 + mt * 16 + gr) * RS + kc) / 2 + gc;
                ah[0] = sa_h[off];                ah[1] = sa_h[off + 4 * RS];
                ah[2] = sa_h[off + 4];            ah[3] = sa_h[off + 4 * RS + 4];
                al[0] = sa_l[off];                al[1] = sa_l[off + 4 * RS];
                al[2] = sa_l[off + 4];            al[3] = sa_l[off + 4 * RS + 4];
                #pragma unroll
                for (int nt = 0; nt < 4; nt++) {
                    mma16(acc[mt][nt], ah, bh[nt]);
                    mma16(acc[mt][nt], ah, bl[nt]);
                    mma16(acc[mt][nt], al, bh[nt]);
                }
            }
        }
        __syncthreads();
        if (c + 2 < NCH) {
            prefetch(sb32 + st * STG, i0, j0, (c + 2) * 32, tid);
            cpa_commit();
        }
    }

    // ---------- per-thread attribute caches ----------
    float sqjv[8]; int labj[8], sbjj[8], jg[8];      // cols: q = nt*2+e
    #pragma unroll
    for (int q = 0; q < 8; q++) {
        int cl = wx * 32 + (q >> 1) * 8 + 2 * gc + (q & 1);
        sqjv[q] = s_sqj[cl]; labj[q] = s_labj[cl]; sbjj[q] = s_sbjj[cl];
        jg[q] = j0 + cl;
    }
    float sqiv[8]; int labi[8], sbji[8], igr[8];     // rows: r = mt*2+h
    #pragma unroll
    for (int r = 0; r < 8; r++) {
        int rl = wy * 64 + (r >> 1) * 16 + gr + (r & 1) * 8;
        sqiv[r] = s_sqi[rl]; labi[r] = s_labi[rl]; sbji[r] = s_sbji[rl];
        igr[r] = i0 + rl;
    }

    // ---------- row mining (rows of this tile vs its 128 cols) ----------
    #pragma unroll
    for (int r = 0; r < 8; r++) {
        float bpd = -1.f;    int bpi = -1;
        float bnd = 3.4e38f; int bni = -1;
        #pragma unroll
        for (int q = 0; q < 8; q++) {
            float d2 = fmaxf(fmaf(-2.f, acc[r >> 1][q >> 1][(r & 1) * 2 + (q & 1)],
                                  sqiv[r] + sqjv[q]), 0.f);
            if (sbjj[q] == sbji[r]) {
                if (labj[q] == labi[r]) {
                    if (jg[q] != igr[r] && d2 > bpd) { bpd = d2; bpi = jg[q]; }
                } else {
                    if (d2 < bnd) { bnd = d2; bni = jg[q]; }
                }
            }
        }
        #pragma unroll
        for (int o = 1; o < 4; o <<= 1) {        // merge 4 gc lanes sharing a row
            float od = __shfl_xor_sync(0xffffffffu, bpd, o);
            int   oi = __shfl_xor_sync(0xffffffffu, bpi, o);
            if (oi >= 0 && (bpi < 0 || od > bpd || (od == bpd && oi < bpi))) { bpd = od; bpi = oi; }
            od = __shfl_xor_sync(0xffffffffu, bnd, o);
            oi = __shfl_xor_sync(0xffffffffu, bni, o);
            if (oi >= 0 && (bni < 0 || od < bnd || (od == bnd && oi < bni))) { bnd = od; bni = oi; }
        }
        if (gc == 0) {
            if (bpi >= 0)
                atomicMax(&g_bp[igr[r]], ((unsigned long long)__float_as_uint(bpd) << 32) |
                                         (unsigned long long)(~(unsigned)bpi));
            if (bni >= 0)
                atomicMin(&g_bn[igr[r]], ((unsigned long long)__float_as_uint(bnd) << 32) |
                                         (unsigned long long)(unsigned)bni);
        }
    }

    // ---------- column mining (transpose view; skip on diagonal tiles) ----------
    if (!diag) {
        #pragma unroll
        for (int q = 0; q < 8; q++) {
            float bpd = -1.f;    int bpi = -1;
            float bnd = 3.4e38f; int bni = -1;
            #pragma unroll
            for (int r = 0; r < 8; r++) {
                float d2 = fmaxf(fmaf(-2.f, acc[r >> 1][q >> 1][(r & 1) * 2 + (q & 1)],
                                      sqiv[r] + sqjv[q]), 0.f);
                if (sbji[r] == sbjj[q]) {
                    if (labi[r] == labj[q]) {
                        if (d2 > bpd) { bpd = d2; bpi = igr[r]; }
                    } else {
                        if (d2 < bnd) { bnd = d2; bni = igr[r]; }
                    }
                }
            }
            #pragma unroll
            for (int o = 4; o < 32; o <<= 1) {   // merge 8 gr lanes sharing a column
                float od = __shfl_xor_sync(0xffffffffu, bpd, o);
                int   oi = __shfl_xor_sync(0xffffffffu, bpi, o);
                if (oi >= 0 && (bpi < 0 || od > bpd || (od == bpd && oi < bpi))) { bpd = od; bpi = oi; }
                od = __shfl_xor_sync(0xffffffffu, bnd, o);
                oi = __shfl_xor_sync(0xffffffffu, bni, o);
                if (oi >= 0 && (bni < 0 || od < bnd || (od == bnd && oi < bni))) { bnd = od; bni = oi; }
            }
            if (gr == 0) {
                if (bpi >= 0)
                    atomicMax(&g_bp[jg[q]], ((unsigned long long)__float_as_uint(bpd) << 32) |
                                            (unsigned long long)(~(unsigned)bpi));
                if (bni >= 0)
                    atomicMin(&g_bn[jg[q]], ((unsigned long long)__float_as_uint(bnd) << 32) |
                                            (unsigned long long)(unsigned)bni);
            }
        }
    }
}

// ---------------- per-row triplet loss (exact fp32 recompute with +EPS) ----------------
__global__ void loss_k(const float* __restrict__ emb) {
    int gw   = (blockIdx.x * blockDim.x + threadIdx.x) >> 5;
    int lane = threadIdx.x & 31;
    if (gw >= Nn) return;
    unsigned long long pp = g_bp[gw], pn = g_bn[gw];
    int p = (pp == 0ull)  ? -1 : (int)(~(unsigned)(pp & 0xFFFFFFFFull));
    int q = (pn == ~0ull) ? -1 : (int)(unsigned)(pn & 0xFFFFFFFFull);
    bool valid = (p >= 0) && (q >= 0);
    float per = 0.f;
    if (valid) {
        const float4* ei = (const float4*)(emb + (size_t)gw * Dd);
        const float4* ep = (const float4*)(emb + (size_t)p  * Dd);
        const float4* en = (const float4*)(emb + (size_t)q  * Dd);
        float sp = 0.f, sn = 0.f;
        const float eps = 1e-6f;
        #pragma unroll
        for (int t = 0; t < 2; t++) {
            float4 a = ei[lane + t * 32], b = ep[lane + t * 32], c = en[lane + t * 32];
            float d;
            d = a.x - b.x + eps; sp += d * d;
            d = a.y - b.y + eps; sp += d * d;
            d = a.z - b.z + eps; sp += d * d;
            d = a.w - b.w + eps; sp += d * d;
            d = a.x - c.x + eps; sn += d * d;
            d = a.y - c.y + eps; sn += d * d;
            d = a.z - c.z + eps; sn += d * d;
            d = a.w - c.w + eps; sn += d * d;
        }
        #pragma unroll
        for (int o = 16; o; o >>= 1) {
            sp += __shfl_xor_sync(0xffffffffu, sp, o);
            sn += __shfl_xor_sync(0xffffffffu, sn, o);
        }
        per = fmaxf(sqrtf(sp) - sqrtf(sn) + 1.0f, 0.f);
    }
    if (!lane) { g_per[gw] = per; g_val[gw] = valid ? 1 : 0; }
}

// ---------------- final scalar reduction ----------------
__global__ void reduce_k(float* __restrict__ out) {
    __shared__ double ss[256];
    __shared__ int    sc[256];
    int tid = threadIdx.x;
    double s = 0.0; int c = 0;
    for (int i = tid; i < Nn; i += 256) { s += (double)g_per[i]; c += g_val[i]; }
    ss[tid] = s; sc[tid] = c;
    __syncthreads();
    for (int o = 128; o; o >>= 1) {
        if (tid < o) { ss[tid] += ss[tid + o]; sc[tid] += sc[tid + o]; }
        __syncthreads();
    }
    if (!tid) {
        int cnt = sc[0] > 1 ? sc[0] : 1;
        out[0] = (float)(ss[0] / (double)cnt);
    }
}

extern "C" void kernel_launch(void* const* d_in, const int* in_sizes, int n_in,
                              void* d_out, int out_size) {
    const float* emb    = (const float*)d_in[0];
    const int*   labels = (const int*)d_in[1];
    const int*   sbjv   = (const int*)d_in[2];
    float* out = (float*)d_out;

    cudaFuncSetAttribute(mine_k, cudaFuncAttributeMaxDynamicSharedMemorySize, SMEM_DYN);

    prep_k<<<Nn / 8, 256>>>(emb);
    mine_k<<<NTRI, 256, SMEM_DYN>>>(labels, sbjv);
    loss_k<<<Nn / 8, 256>>>(emb);
    reduce_k<<<1, 256>>>(out);
}

// round 6
// speedup vs baseline: 6.9683x; 1.1459x over previous
#include <cuda_runtime.h>
#include <cuda_bf16.h>
#include <cstdint>
#include <math.h>

#define Nn 8192
#define Dd 256
#define TM 128
#define TN 128
#define NT 64                 // tiles per dimension
#define NTRI (NT*(NT+1)/2)    // 2080 upper-tri tiles
#define NCH 8                 // K chunks of 32 elements
#define GRID_MINE 304         // persistent CTAs (2/SM on 152-SM GB300)

#define RS     40             // smem row stride in bf16 elems (80B, conflict-free)
#define TILE_B 10240          // 128 rows * 80B
#define A_H    0
#define A_L    10240
#define B_H    20480
#define STG    30720          // bytes per pipeline stage (Ah+Al+Bh)
#define META   61440
#define SMEM_DYN (META + 6*128*4)

__device__ __align__(256) __nv_bfloat16 g_hi[Nn*Dd];
__device__ __align__(256) __nv_bfloat16 g_lo[Nn*Dd];
__device__ float g_sqn[Nn];
__device__ unsigned long long g_bp[Nn];
__device__ unsigned long long g_bn[Nn];
__device__ double g_sum;
__device__ int    g_cnt;

// ---------------- PTX helpers ----------------
__device__ __forceinline__ uint32_t smem_u32(const void* p) {
    uint32_t a;
    asm("{ .reg .u64 t; cvta.to.shared.u64 t, %1; cvt.u32.u64 %0, t; }" : "=r"(a) : "l"(p));
    return a;
}
__device__ __forceinline__ void cpa16(uint32_t dst, const __nv_bfloat16* src) {
    asm volatile("cp.async.cg.shared.global [%0], [%1], 16;" :: "r"(dst), "l"(src));
}
__device__ __forceinline__ void cpa_commit() { asm volatile("cp.async.commit_group;" ::: "memory"); }
__device__ __forceinline__ void cpa_wait1()  { asm volatile("cp.async.wait_group 1;" ::: "memory"); }
__device__ __forceinline__ void cpa_wait0()  { asm volatile("cp.async.wait_group 0;" ::: "memory"); }

__device__ __forceinline__ void mma16(float* c, const uint32_t* a, const uint32_t* b) {
    asm volatile("mma.sync.aligned.m16n8k16.row.col.f32.bf16.bf16.f32 "
        "{%0,%1,%2,%3}, {%4,%5,%6,%7}, {%8,%9}, {%0,%1,%2,%3};"
        : "+f"(c[0]), "+f"(c[1]), "+f"(c[2]), "+f"(c[3])
        : "r"(a[0]), "r"(a[1]), "r"(a[2]), "r"(a[3]), "r"(b[0]), "r"(b[1]));
}

// ---------------- prep: bf16 hi/lo split + sq norms + init ----------------
__global__ void prep_k(const float* __restrict__ emb) {
    if (blockIdx.x == 0 && threadIdx.x == 0) { g_sum = 0.0; g_cnt = 0; }
    int gw   = (blockIdx.x * blockDim.x + threadIdx.x) >> 5;
    int lane = threadIdx.x & 31;
    if (gw >= Nn) return;
    const float4* p = (const float4*)(emb + (size_t)gw * Dd);
    __nv_bfloat162* ph = (__nv_bfloat162*)(g_hi + (size_t)gw * Dd);
    __nv_bfloat162* pl = (__nv_bfloat162*)(g_lo + (size_t)gw * Dd);
    float s = 0.f;
    #pragma unroll
    for (int q = 0; q < 2; q++) {
        int e = lane + q * 32;
        float4 v = p[e];
        __nv_bfloat16 hx = __float2bfloat16_rn(v.x), hy = __float2bfloat16_rn(v.y);
        __nv_bfloat16 hz = __float2bfloat16_rn(v.z), hw = __float2bfloat16_rn(v.w);
        __nv_bfloat16 lx = __float2bfloat16_rn(v.x - __bfloat162float(hx));
        __nv_bfloat16 ly = __float2bfloat16_rn(v.y - __bfloat162float(hy));
        __nv_bfloat16 lz = __float2bfloat16_rn(v.z - __bfloat162float(hz));
        __nv_bfloat16 lw = __float2bfloat16_rn(v.w - __bfloat162float(hw));
        ph[2*e]   = __nv_bfloat162(hx, hy);
        ph[2*e+1] = __nv_bfloat162(hz, hw);
        pl[2*e]   = __nv_bfloat162(lx, ly);
        pl[2*e+1] = __nv_bfloat162(lz, lw);
        s += v.x * v.x + v.y * v.y + v.z * v.z + v.w * v.w;
    }
    #pragma unroll
    for (int o = 16; o; o >>= 1) s += __shfl_xor_sync(0xffffffffu, s, o);
    if (!lane) {
        g_sqn[gw] = s;
        g_bp[gw] = 0ull;
        g_bn[gw] = ~0ull;
    }
}

// ---------------- chunk loader: gmem -> padded row-major smem via cp.async ----------------
__device__ __forceinline__ void prefetch(uint32_t stg32, int i0, int j0, int kk, int tid) {
    #pragma unroll
    for (int t = 0; t < 6; t++) {
        int u    = tid + t * 256;          // 0..1535
        int tile = u >> 9;                 // 0:Ah 1:Al 2:Bh
        int w    = u & 511;
        int row  = w >> 2;                 // 0..127
        int k4   = w & 3;                  // 0..3 (16B = 8 bf16 each)
        uint32_t dst = stg32 + tile * TILE_B + row * (RS * 2) + k4 * 16;
        int base = (tile < 2 ? i0 : j0) + row;
        const __nv_bfloat16* g = (tile == 1) ? g_lo : g_hi;
        cpa16(dst, g + (size_t)base * Dd + kk + k4 * 8);
    }
}

// ---------------- fused 2xbf16 distance GEMM + bidirectional hardest mining ----------------
__global__ __launch_bounds__(256, 2)
void mine_k(const int* __restrict__ labels, const int* __restrict__ sbj) {
    extern __shared__ __align__(16) char sb[];
    const uint32_t sb32 = smem_u32(sb);

    const int tid  = threadIdx.x;
    const int wid  = tid >> 5;
    const int lane = tid & 31;
    const int gr   = lane >> 2;     // 0..7
    const int gc   = lane & 3;      // 0..3
    const int wy   = wid >> 2;      // 0..1  (M)
    const int wx   = wid & 3;       // 0..3  (N)

    int*   s_labi = (int*)  (sb + META);
    int*   s_sbji = (int*)  (sb + META + 512);
    float* s_sqi  = (float*)(sb + META + 1024);
    int*   s_labj = (int*)  (sb + META + 1536);
    int*   s_sbjj = (int*)  (sb + META + 2048);
    float* s_sqj  = (float*)(sb + META + 2560);

    for (int u = blockIdx.x; u < NTRI; u += GRID_MINE) {
        // decode triangular tile index: tiles (ta, tb), ta <= tb
        int ta = (int)((129.0 - sqrt(129.0 * 129.0 - 8.0 * (double)u)) * 0.5);
        while ((ta + 1) * NT - ((ta + 1) * ta) / 2 <= u) ta++;
        while (ta * NT - (ta * (ta - 1)) / 2 > u) ta--;
        const int tb = ta + (u - (ta * NT - (ta * (ta - 1)) / 2));
        const int i0 = ta * TM;
        const int j0 = tb * TN;
        const bool diag = (ta == tb);

        __syncthreads();   // previous epilogue done reading meta
        if (tid < 128) {
            s_labi[tid] = labels[i0 + tid];
            s_sbji[tid] = sbj[i0 + tid];
            s_sqi[tid]  = g_sqn[i0 + tid];
            s_labj[tid] = labels[j0 + tid];
            s_sbjj[tid] = sbj[j0 + tid];
            s_sqj[tid]  = g_sqn[j0 + tid];
        }

        prefetch(sb32,       i0, j0,  0, tid); cpa_commit();
        prefetch(sb32 + STG, i0, j0, 32, tid); cpa_commit();

        float acc[4][4][4];
        #pragma unroll
        for (int mt = 0; mt < 4; mt++)
            #pragma unroll
            for (int nt = 0; nt < 4; nt++)
                #pragma unroll
                for (int q = 0; q < 4; q++) acc[mt][nt][q] = 0.f;

        for (int c = 0; c < NCH; c++) {
            const int st = c & 1;
            if (c < NCH - 1) cpa_wait1(); else cpa_wait0();
            __syncthreads();

            const uint32_t* sa_h = (const uint32_t*)(sb + st * STG + A_H);
            const uint32_t* sa_l = (const uint32_t*)(sb + st * STG + A_L);
            const uint32_t* sb_h = (const uint32_t*)(sb + st * STG + B_H);

            #pragma unroll
            for (int kc = 0; kc < 32; kc += 16) {
                uint32_t bh[4][2];
                #pragma unroll
                for (int nt = 0; nt < 4; nt++) {
                    int off = ((wx * 32 + nt * 8 + gr) * RS + kc) / 2 + gc;
                    bh[nt][0] = sb_h[off];     bh[nt][1] = sb_h[off + 4];
                }
                #pragma unroll
                for (int mt = 0; mt < 4; mt++) {
                    uint32_t ah[4], al[4];
                    int off = ((wy * 64 + mt * 16 + gr) * RS + kc) / 2 + gc;
                    ah[0] = sa_h[off];                ah[1] = sa_h[off + 4 * RS];
                    ah[2] = sa_h[off + 4];            ah[3] = sa_h[off + 4 * RS + 4];
                    al[0] = sa_l[off];                al[1] = sa_l[off + 4 * RS];
                    al[2] = sa_l[off + 4];            al[3] = sa_l[off + 4 * RS + 4];
                    #pragma unroll
                    for (int nt = 0; nt < 4; nt++) {
                        mma16(acc[mt][nt], ah, bh[nt]);
                        mma16(acc[mt][nt], al, bh[nt]);
                    }
                }
            }
            __syncthreads();
            if (c + 2 < NCH) {
                prefetch(sb32 + st * STG, i0, j0, (c + 2) * 32, tid);
                cpa_commit();
            }
        }

        // ---------- per-thread attribute caches ----------
        float sqjv[8]; int labj[8], sbjj[8], jg[8];      // cols: q = nt*2+e
        #pragma unroll
        for (int q = 0; q < 8; q++) {
            int cl = wx * 32 + (q >> 1) * 8 + 2 * gc + (q & 1);
            sqjv[q] = s_sqj[cl]; labj[q] = s_labj[cl]; sbjj[q] = s_sbjj[cl];
            jg[q] = j0 + cl;
        }
        float sqiv[8]; int labi[8], sbji[8], igr[8];     // rows: r = mt*2+h
        #pragma unroll
        for (int r = 0; r < 8; r++) {
            int rl = wy * 64 + (r >> 1) * 16 + gr + (r & 1) * 8;
            sqiv[r] = s_sqi[rl]; labi[r] = s_labi[rl]; sbji[r] = s_sbji[rl];
            igr[r] = i0 + rl;
        }

        // ---------- row mining ----------
        #pragma unroll
        for (int r = 0; r < 8; r++) {
            float bpd = -1.f;    int bpi = -1;
            float bnd = 3.4e38f; int bni = -1;
            #pragma unroll
            for (int q = 0; q < 8; q++) {
                float d2 = fmaxf(fmaf(-2.f, acc[r >> 1][q >> 1][(r & 1) * 2 + (q & 1)],
                                      sqiv[r] + sqjv[q]), 0.f);
                if (sbjj[q] == sbji[r]) {
                    if (labj[q] == labi[r]) {
                        if (jg[q] != igr[r] && d2 > bpd) { bpd = d2; bpi = jg[q]; }
                    } else {
                        if (d2 < bnd) { bnd = d2; bni = jg[q]; }
                    }
                }
            }
            #pragma unroll
            for (int o = 1; o < 4; o <<= 1) {
                float od = __shfl_xor_sync(0xffffffffu, bpd, o);
                int   oi = __shfl_xor_sync(0xffffffffu, bpi, o);
                if (oi >= 0 && (bpi < 0 || od > bpd || (od == bpd && oi < bpi))) { bpd = od; bpi = oi; }
                od = __shfl_xor_sync(0xffffffffu, bnd, o);
                oi = __shfl_xor_sync(0xffffffffu, bni, o);
                if (oi >= 0 && (bni < 0 || od < bnd || (od == bnd && oi < bni))) { bnd = od; bni = oi; }
            }
            if (gc == 0) {
                if (bpi >= 0)
                    atomicMax(&g_bp[igr[r]], ((unsigned long long)__float_as_uint(bpd) << 32) |
                                             (unsigned long long)(~(unsigned)bpi));
                if (bni >= 0)
                    atomicMin(&g_bn[igr[r]], ((unsigned long long)__float_as_uint(bnd) << 32) |
                                             (unsigned long long)(unsigned)bni);
            }
        }

        // ---------- column mining (transpose view; skip on diagonal tiles) ----------
        if (!diag) {
            #pragma unroll
            for (int q = 0; q < 8; q++) {
                float bpd = -1.f;    int bpi = -1;
                float bnd = 3.4e38f; int bni = -1;
                #pragma unroll
                for (int r = 0; r < 8; r++) {
                    float d2 = fmaxf(fmaf(-2.f, acc[r >> 1][q >> 1][(r & 1) * 2 + (q & 1)],
                                          sqiv[r] + sqjv[q]), 0.f);
                    if (sbji[r] == sbjj[q]) {
                        if (labi[r] == labj[q]) {
                            if (d2 > bpd) { bpd = d2; bpi = igr[r]; }
                        } else {
                            if (d2 < bnd) { bnd = d2; bni = igr[r]; }
                        }
                    }
                }
                #pragma unroll
                for (int o = 4; o < 32; o <<= 1) {
                    float od = __shfl_xor_sync(0xffffffffu, bpd, o);
                    int   oi = __shfl_xor_sync(0xffffffffu, bpi, o);
                    if (oi >= 0 && (bpi < 0 || od > bpd || (od == bpd && oi < bpi))) { bpd = od; bpi = oi; }
                    od = __shfl_xor_sync(0xffffffffu, bnd, o);
                    oi = __shfl_xor_sync(0xffffffffu, bni, o);
                    if (oi >= 0 && (bni < 0 || od < bnd || (od == bnd && oi < bni))) { bnd = od; bni = oi; }
                }
                if (gr == 0) {
                    if (bpi >= 0)
                        atomicMax(&g_bp[jg[q]], ((unsigned long long)__float_as_uint(bpd) << 32) |
                                                (unsigned long long)(~(unsigned)bpi));
                    if (bni >= 0)
                        atomicMin(&g_bn[jg[q]], ((unsigned long long)__float_as_uint(bnd) << 32) |
                                                (unsigned long long)(unsigned)bni);
                }
            }
        }
    }
}

// ---------------- per-row triplet loss (exact fp32, +EPS) fused with reduction ----------------
__global__ void loss_k(const float* __restrict__ emb) {
    int gw   = (blockIdx.x * blockDim.x + threadIdx.x) >> 5;
    int lane = threadIdx.x & 31;
    if (gw >= Nn) return;
    unsigned long long pp = g_bp[gw], pn = g_bn[gw];
    int p = (pp == 0ull)  ? -1 : (int)(~(unsigned)(pp & 0xFFFFFFFFull));
    int q = (pn == ~0ull) ? -1 : (int)(unsigned)(pn & 0xFFFFFFFFull);
    bool valid = (p >= 0) && (q >= 0);
    float per = 0.f;
    if (valid) {
        const float4* ei = (const float4*)(emb + (size_t)gw * Dd);
        const float4* ep = (const float4*)(emb + (size_t)p  * Dd);
        const float4* en = (const float4*)(emb + (size_t)q  * Dd);
        float sp = 0.f, sn = 0.f;
        const float eps = 1e-6f;
        #pragma unroll
        for (int t = 0; t < 2; t++) {
            float4 a = ei[lane + t * 32], b = ep[lane + t * 32], c = en[lane + t * 32];
            float d;
            d = a.x - b.x + eps; sp += d * d;
            d = a.y - b.y + eps; sp += d * d;
            d = a.z - b.z + eps; sp += d * d;
            d = a.w - b.w + eps; sp += d * d;
            d = a.x - c.x + eps; sn += d * d;
            d = a.y - c.y + eps; sn += d * d;
            d = a.z - c.z + eps; sn += d * d;
            d = a.w - c.w + eps; sn += d * d;
        }
        #pragma unroll
        for (int o = 16; o; o >>= 1) {
            sp += __shfl_xor_sync(0xffffffffu, sp, o);
            sn += __shfl_xor_sync(0xffffffffu, sn, o);
        }
        per = fmaxf(sqrtf(sp) - sqrtf(sn) + 1.0f, 0.f);
    }
    if (!lane && valid) {
        atomicAdd(&g_sum, (double)per);
        atomicAdd(&g_cnt, 1);
    }
}

// ---------------- finalize ----------------
__global__ void final_k(float* __restrict__ out) {
    int cnt = g_cnt > 1 ? g_cnt : 1;
    out[0] = (float)(g_sum / (double)cnt);
}

extern "C" void kernel_launch(void* const* d_in, const int* in_sizes, int n_in,
                              void* d_out, int out_size) {
    const float* emb    = (const float*)d_in[0];
    const int*   labels = (const int*)d_in[1];
    const int*   sbjv   = (const int*)d_in[2];
    float* out = (float*)d_out;

    cudaFuncSetAttribute(mine_k, cudaFuncAttributeMaxDynamicSharedMemorySize, SMEM_DYN);

    prep_k<<<Nn / 8, 256>>>(emb);
    mine_k<<<GRID_MINE, 256, SMEM_DYN>>>(labels, sbjv);
    loss_k<<<Nn / 8, 256>>>(emb);
    final_k<<<1, 1>>>(out);
}

// round 7
// speedup vs baseline: 7.0274x; 1.0085x over previous
#include <cuda_runtime.h>
#include <cuda_bf16.h>
#include <cstdint>
#include <math.h>

#define Nn 8192
#define Dd 256
#define TM 128
#define TN 128
#define NT 64                 // tiles per dimension
#define NTRI (NT*(NT+1)/2)    // 2080 upper-tri tiles
#define NCH 8                 // K chunks of 32 elements
#define GRID_MINE 304         // persistent CTAs (2/SM on 152-SM GB300)

#define RS     40             // smem row stride in bf16 elems (80B, conflict-free for LDSM)
#define RB     80             // row stride bytes
#define TILE_B 10240          // 128 rows * 80B
#define A_H    0
#define A_L    10240
#define B_H    20480
#define STG    30720          // bytes per pipeline stage (Ah+Al+Bh)
#define META   61440
#define SMEM_DYN (META + 6*128*4)

__device__ __align__(256) __nv_bfloat16 g_hi[Nn*Dd];
__device__ __align__(256) __nv_bfloat16 g_lo[Nn*Dd];
__device__ float g_sqn[Nn];
__device__ unsigned long long g_bp[Nn];
__device__ unsigned long long g_bn[Nn];
__device__ double g_sum;
__device__ int    g_cnt;

// ---------------- PTX helpers ----------------
__device__ __forceinline__ uint32_t smem_u32(const void* p) {
    uint32_t a;
    asm("{ .reg .u64 t; cvta.to.shared.u64 t, %1; cvt.u32.u64 %0, t; }" : "=r"(a) : "l"(p));
    return a;
}
__device__ __forceinline__ void cpa16(uint32_t dst, const __nv_bfloat16* src) {
    asm volatile("cp.async.cg.shared.global [%0], [%1], 16;" :: "r"(dst), "l"(src));
}
__device__ __forceinline__ void cpa_commit() { asm volatile("cp.async.commit_group;" ::: "memory"); }
__device__ __forceinline__ void cpa_wait1()  { asm volatile("cp.async.wait_group 1;" ::: "memory"); }
__device__ __forceinline__ void cpa_wait0()  { asm volatile("cp.async.wait_group 0;" ::: "memory"); }

__device__ __forceinline__ void ldsm4(uint32_t* r, uint32_t addr) {
    asm volatile("ldmatrix.sync.aligned.m8n8.x4.shared.b16 {%0,%1,%2,%3}, [%4];"
        : "=r"(r[0]), "=r"(r[1]), "=r"(r[2]), "=r"(r[3]) : "r"(addr));
}
__device__ __forceinline__ void mma16(float* c, const uint32_t* a, uint32_t b0, uint32_t b1) {
    asm volatile("mma.sync.aligned.m16n8k16.row.col.f32.bf16.bf16.f32 "
        "{%0,%1,%2,%3}, {%4,%5,%6,%7}, {%8,%9}, {%0,%1,%2,%3};"
        : "+f"(c[0]), "+f"(c[1]), "+f"(c[2]), "+f"(c[3])
        : "r"(a[0]), "r"(a[1]), "r"(a[2]), "r"(a[3]), "r"(b0), "r"(b1));
}

// ---------------- prep: bf16 hi/lo split + sq norms + init ----------------
__global__ void prep_k(const float* __restrict__ emb) {
    if (blockIdx.x == 0 && threadIdx.x == 0) { g_sum = 0.0; g_cnt = 0; }
    int gw   = (blockIdx.x * blockDim.x + threadIdx.x) >> 5;
    int lane = threadIdx.x & 31;
    if (gw >= Nn) return;
    const float4* p = (const float4*)(emb + (size_t)gw * Dd);
    __nv_bfloat162* ph = (__nv_bfloat162*)(g_hi + (size_t)gw * Dd);
    __nv_bfloat162* pl = (__nv_bfloat162*)(g_lo + (size_t)gw * Dd);
    float s = 0.f;
    #pragma unroll
    for (int q = 0; q < 2; q++) {
        int e = lane + q * 32;
        float4 v = p[e];
        __nv_bfloat16 hx = __float2bfloat16_rn(v.x), hy = __float2bfloat16_rn(v.y);
        __nv_bfloat16 hz = __float2bfloat16_rn(v.z), hw = __float2bfloat16_rn(v.w);
        __nv_bfloat16 lx = __float2bfloat16_rn(v.x - __bfloat162float(hx));
        __nv_bfloat16 ly = __float2bfloat16_rn(v.y - __bfloat162float(hy));
        __nv_bfloat16 lz = __float2bfloat16_rn(v.z - __bfloat162float(hz));
        __nv_bfloat16 lw = __float2bfloat16_rn(v.w - __bfloat162float(hw));
        ph[2*e]   = __nv_bfloat162(hx, hy);
        ph[2*e+1] = __nv_bfloat162(hz, hw);
        pl[2*e]   = __nv_bfloat162(lx, ly);
        pl[2*e+1] = __nv_bfloat162(lz, lw);
        s += v.x * v.x + v.y * v.y + v.z * v.z + v.w * v.w;
    }
    #pragma unroll
    for (int o = 16; o; o >>= 1) s += __shfl_xor_sync(0xffffffffu, s, o);
    if (!lane) {
        g_sqn[gw] = s;
        g_bp[gw] = 0ull;
        g_bn[gw] = ~0ull;
    }
}

// ---------------- chunk loader: gmem -> padded row-major smem via cp.async ----------------
__device__ __forceinline__ void prefetch(uint32_t stg32, int i0, int j0, int kk, int tid) {
    #pragma unroll
    for (int t = 0; t < 6; t++) {
        int u    = tid + t * 256;          // 0..1535
        int tile = u >> 9;                 // 0:Ah 1:Al 2:Bh
        int w    = u & 511;
        int row  = w >> 2;                 // 0..127
        int k4   = w & 3;                  // 0..3 (16B = 8 bf16 each)
        uint32_t dst = stg32 + tile * TILE_B + row * RB + k4 * 16;
        int base = (tile < 2 ? i0 : j0) + row;
        const __nv_bfloat16* g = (tile == 1) ? g_lo : g_hi;
        cpa16(dst, g + (size_t)base * Dd + kk + k4 * 8);
    }
}

// ---------------- fused 2xbf16 distance GEMM (ldmatrix feed) + bidirectional mining ----------------
__global__ __launch_bounds__(256, 2)
void mine_k(const int* __restrict__ labels, const int* __restrict__ sbj) {
    extern __shared__ __align__(16) char sb[];
    const uint32_t sb32 = smem_u32(sb);

    const int tid  = threadIdx.x;
    const int wid  = tid >> 5;
    const int lane = tid & 31;
    const int gr   = lane >> 2;     // 0..7
    const int gc   = lane & 3;      // 0..3
    const int wy   = wid >> 2;      // 0..1  (M)
    const int wx   = wid & 3;       // 0..3  (N)

    // per-lane ldmatrix base offsets (row = lane&15, k-half = lane>>4)
    const uint32_t lrow = lane & 15, khalf = lane >> 4;
    const uint32_t aoff = (wy * 64 + lrow) * RB + khalf * 16;
    const uint32_t boff = (wx * 32 + lrow) * RB + khalf * 16;

    int*   s_labi = (int*)  (sb + META);
    int*   s_sbji = (int*)  (sb + META + 512);
    float* s_sqi  = (float*)(sb + META + 1024);
    int*   s_labj = (int*)  (sb + META + 1536);
    int*   s_sbjj = (int*)  (sb + META + 2048);
    float* s_sqj  = (float*)(sb + META + 2560);

    for (int u = blockIdx.x; u < NTRI; u += GRID_MINE) {
        int ta = (int)((129.0 - sqrt(129.0 * 129.0 - 8.0 * (double)u)) * 0.5);
        while ((ta + 1) * NT - ((ta + 1) * ta) / 2 <= u) ta++;
        while (ta * NT - (ta * (ta - 1)) / 2 > u) ta--;
        const int tb = ta + (u - (ta * NT - (ta * (ta - 1)) / 2));
        const int i0 = ta * TM;
        const int j0 = tb * TN;
        const bool diag = (ta == tb);

        __syncthreads();   // previous epilogue done reading meta
        if (tid < 128) {
            s_labi[tid] = labels[i0 + tid];
            s_sbji[tid] = sbj[i0 + tid];
            s_sqi[tid]  = g_sqn[i0 + tid];
            s_labj[tid] = labels[j0 + tid];
            s_sbjj[tid] = sbj[j0 + tid];
            s_sqj[tid]  = g_sqn[j0 + tid];
        }

        prefetch(sb32,       i0, j0,  0, tid); cpa_commit();
        prefetch(sb32 + STG, i0, j0, 32, tid); cpa_commit();

        float acc[4][4][4];
        #pragma unroll
        for (int mt = 0; mt < 4; mt++)
            #pragma unroll
            for (int nt = 0; nt < 4; nt++)
                #pragma unroll
                for (int q = 0; q < 4; q++) acc[mt][nt][q] = 0.f;

        for (int c = 0; c < NCH; c++) {
            const int st = c & 1;
            if (c < NCH - 1) cpa_wait1(); else cpa_wait0();
            __syncthreads();

            const uint32_t stb = sb32 + st * STG;
            #pragma unroll
            for (int kc2 = 0; kc2 < 2; kc2++) {
                const uint32_t kb = kc2 * 32;          // 16 bf16 = 32B
                uint32_t B0[4], B1[4];
                ldsm4(B0, stb + B_H + boff + kb);          // n-tiles 0,1
                ldsm4(B1, stb + B_H + boff + 16 * RB + kb); // n-tiles 2,3
                #pragma unroll
                for (int mt = 0; mt < 4; mt++) {
                    uint32_t ah[4], al[4];
                    const uint32_t ab = aoff + mt * 16 * RB + kb;
                    ldsm4(ah, stb + A_H + ab);
                    ldsm4(al, stb + A_L + ab);
                    mma16(acc[mt][0], ah, B0[0], B0[2]);
                    mma16(acc[mt][0], al, B0[0], B0[2]);
                    mma16(acc[mt][1], ah, B0[1], B0[3]);
                    mma16(acc[mt][1], al, B0[1], B0[3]);
                    mma16(acc[mt][2], ah, B1[0], B1[2]);
                    mma16(acc[mt][2], al, B1[0], B1[2]);
                    mma16(acc[mt][3], ah, B1[1], B1[3]);
                    mma16(acc[mt][3], al, B1[1], B1[3]);
                }
            }
            __syncthreads();
            if (c + 2 < NCH) {
                prefetch(sb32 + st * STG, i0, j0, (c + 2) * 32, tid);
                cpa_commit();
            }
        }

        // ---------- per-thread attribute caches ----------
        float sqjv[8]; int labj[8], sbjj[8], jg[8];      // cols: q = nt*2+e
        #pragma unroll
        for (int q = 0; q < 8; q++) {
            int cl = wx * 32 + (q >> 1) * 8 + 2 * gc + (q & 1);
            sqjv[q] = s_sqj[cl]; labj[q] = s_labj[cl]; sbjj[q] = s_sbjj[cl];
            jg[q] = j0 + cl;
        }
        float sqiv[8]; int labi[8], sbji[8], igr[8];     // rows: r = mt*2+h
        #pragma unroll
        for (int r = 0; r < 8; r++) {
            int rl = wy * 64 + (r >> 1) * 16 + gr + (r & 1) * 8;
            sqiv[r] = s_sqi[rl]; labi[r] = s_labi[rl]; sbji[r] = s_sbji[rl];
            igr[r] = i0 + rl;
        }

        // ---------- row mining ----------
        #pragma unroll
        for (int r = 0; r < 8; r++) {
            float bpd = -1.f;    int bpi = -1;
            float bnd = 3.4e38f; int bni = -1;
            #pragma unroll
            for (int q = 0; q < 8; q++) {
                float d2 = fmaxf(fmaf(-2.f, acc[r >> 1][q >> 1][(r & 1) * 2 + (q & 1)],
                                      sqiv[r] + sqjv[q]), 0.f);
                if (sbjj[q] == sbji[r]) {
                    if (labj[q] == labi[r]) {
                        if (jg[q] != igr[r] && d2 > bpd) { bpd = d2; bpi = jg[q]; }
                    } else {
                        if (d2 < bnd) { bnd = d2; bni = jg[q]; }
                    }
                }
            }
            #pragma unroll
            for (int o = 1; o < 4; o <<= 1) {
                float od = __shfl_xor_sync(0xffffffffu, bpd, o);
                int   oi = __shfl_xor_sync(0xffffffffu, bpi, o);
                if (oi >= 0 && (bpi < 0 || od > bpd || (od == bpd && oi < bpi))) { bpd = od; bpi = oi; }
                od = __shfl_xor_sync(0xffffffffu, bnd, o);
                oi = __shfl_xor_sync(0xffffffffu, bni, o);
                if (oi >= 0 && (bni < 0 || od < bnd || (od == bnd && oi < bni))) { bnd = od; bni = oi; }
            }
            if (gc == 0) {
                if (bpi >= 0)
                    atomicMax(&g_bp[igr[r]], ((unsigned long long)__float_as_uint(bpd) << 32) |
                                             (unsigned long long)(~(unsigned)bpi));
                if (bni >= 0)
                    atomicMin(&g_bn[igr[r]], ((unsigned long long)__float_as_uint(bnd) << 32) |
                                             (unsigned long long)(unsigned)bni);
            }
        }

        // ---------- column mining (transpose view; skip on diagonal tiles) ----------
        if (!diag) {
            #pragma unroll
            for (int q = 0; q < 8; q++) {
                float bpd = -1.f;    int bpi = -1;
                float bnd = 3.4e38f; int bni = -1;
                #pragma unroll
                for (int r = 0; r < 8; r++) {
                    float d2 = fmaxf(fmaf(-2.f, acc[r >> 1][q >> 1][(r & 1) * 2 + (q & 1)],
                                          sqiv[r] + sqjv[q]), 0.f);
                    if (sbji[r] == sbjj[q]) {
                        if (labi[r] == labj[q]) {
                            if (d2 > bpd) { bpd = d2; bpi = igr[r]; }
                        } else {
                            if (d2 < bnd) { bnd = d2; bni = igr[r]; }
                        }
                    }
                }
                #pragma unroll
                for (int o = 4; o < 32; o <<= 1) {
                    float od = __shfl_xor_sync(0xffffffffu, bpd, o);
                    int   oi = __shfl_xor_sync(0xffffffffu, bpi, o);
                    if (oi >= 0 && (bpi < 0 || od > bpd || (od == bpd && oi < bpi))) { bpd = od; bpi = oi; }
                    od = __shfl_xor_sync(0xffffffffu, bnd, o);
                    oi = __shfl_xor_sync(0xffffffffu, bni, o);
                    if (oi >= 0 && (bni < 0 || od < bnd || (od == bnd && oi < bni))) { bnd = od; bni = oi; }
                }
                if (gr == 0) {
                    if (bpi >= 0)
                        atomicMax(&g_bp[jg[q]], ((unsigned long long)__float_as_uint(bpd) << 32) |
                                                (unsigned long long)(~(unsigned)bpi));
                    if (bni >= 0)
                        atomicMin(&g_bn[jg[q]], ((unsigned long long)__float_as_uint(bnd) << 32) |
                                                (unsigned long long)(unsigned)bni);
                }
            }
        }
    }
}

// ---------------- per-row triplet loss (exact fp32, +EPS) fused with reduction ----------------
__global__ void loss_k(const float* __restrict__ emb) {
    int gw   = (blockIdx.x * blockDim.x + threadIdx.x) >> 5;
    int lane = threadIdx.x & 31;
    if (gw >= Nn) return;
    unsigned long long pp = g_bp[gw], pn = g_bn[gw];
    int p = (pp == 0ull)  ? -1 : (int)(~(unsigned)(pp & 0xFFFFFFFFull));
    int q = (pn == ~0ull) ? -1 : (int)(unsigned)(pn & 0xFFFFFFFFull);
    bool valid = (p >= 0) && (q >= 0);
    float per = 0.f;
    if (valid) {
        const float4* ei = (const float4*)(emb + (size_t)gw * Dd);
        const float4* ep = (const float4*)(emb + (size_t)p  * Dd);
        const float4* en = (const float4*)(emb + (size_t)q  * Dd);
        float sp = 0.f, sn = 0.f;
        const float eps = 1e-6f;
        #pragma unroll
        for (int t = 0; t < 2; t++) {
            float4 a = ei[lane + t * 32], b = ep[lane + t * 32], c = en[lane + t * 32];
            float d;
            d = a.x - b.x + eps; sp += d * d;
            d = a.y - b.y + eps; sp += d * d;
            d = a.z - b.z + eps; sp += d * d;
            d = a.w - b.w + eps; sp += d * d;
            d = a.x - c.x + eps; sn += d * d;
            d = a.y - c.y + eps; sn += d * d;
            d = a.z - c.z + eps; sn += d * d;
            d = a.w - c.w + eps; sn += d * d;
        }
        #pragma unroll
        for (int o = 16; o; o >>= 1) {
            sp += __shfl_xor_sync(0xffffffffu, sp, o);
            sn += __shfl_xor_sync(0xffffffffu, sn, o);
        }
        per = fmaxf(sqrtf(sp) - sqrtf(sn) + 1.0f, 0.f);
    }
    if (!lane && valid) {
        atomicAdd(&g_sum, (double)per);
        atomicAdd(&g_cnt, 1);
    }
}

// ---------------- finalize ----------------
__global__ void final_k(float* __restrict__ out) {
    int cnt = g_cnt > 1 ? g_cnt : 1;
    out[0] = (float)(g_sum / (double)cnt);
}

extern "C" void kernel_launch(void* const* d_in, const int* in_sizes, int n_in,
                              void* d_out, int out_size) {
    const float* emb    = (const float*)d_in[0];
    const int*   labels = (const int*)d_in[1];
    const int*   sbjv   = (const int*)d_in[2];
    float* out = (float*)d_out;

    cudaFuncSetAttribute(mine_k, cudaFuncAttributeMaxDynamicSharedMemorySize, SMEM_DYN);

    prep_k<<<Nn / 8, 256>>>(emb);
    mine_k<<<GRID_MINE, 256, SMEM_DYN>>>(labels, sbjv);
    loss_k<<<Nn / 8, 256>>>(emb);
    final_k<<<1, 1>>>(out);
}

// round 8
// speedup vs baseline: 8.8838x; 1.2642x over previous
#include <cuda_runtime.h>
#include <cuda_bf16.h>
#include <cstdint>
#include <math.h>

#define Nn 8192
#define Dd 256
#define TM 128
#define TN 128
#define NT 64                 // tiles per dimension
#define NTRI (NT*(NT+1)/2)    // 2080 upper-tri tiles
#define NCH 4                 // K chunks of 64 elements
#define GRID_MINE 304         // persistent CTAs (2/SM on 152-SM GB300)

#define RB     144            // row stride bytes (128B data + 16B pad, LDSM conflict-free)
#define TILE_B 18432          // 128 rows * 144B
#define STG    36864          // bytes per pipeline stage (A + B)
#define META   73728
#define SMEM_DYN (META + 6*128*4)

__device__ __align__(256) __nv_bfloat16 g_hi[Nn*Dd];
__device__ float g_sqn[Nn];
__device__ unsigned long long g_bp[Nn];
__device__ unsigned long long g_bn[Nn];
__device__ double g_sum;
__device__ int    g_cnt;

// ---------------- PTX helpers ----------------
__device__ __forceinline__ uint32_t smem_u32(const void* p) {
    uint32_t a;
    asm("{ .reg .u64 t; cvta.to.shared.u64 t, %1; cvt.u32.u64 %0, t; }" : "=r"(a) : "l"(p));
    return a;
}
__device__ __forceinline__ void cpa16(uint32_t dst, const __nv_bfloat16* src) {
    asm volatile("cp.async.cg.shared.global [%0], [%1], 16;" :: "r"(dst), "l"(src));
}
__device__ __forceinline__ void cpa_commit() { asm volatile("cp.async.commit_group;" ::: "memory"); }
__device__ __forceinline__ void cpa_wait1()  { asm volatile("cp.async.wait_group 1;" ::: "memory"); }
__device__ __forceinline__ void cpa_wait0()  { asm volatile("cp.async.wait_group 0;" ::: "memory"); }

__device__ __forceinline__ void ldsm4(uint32_t* r, uint32_t addr) {
    asm volatile("ldmatrix.sync.aligned.m8n8.x4.shared.b16 {%0,%1,%2,%3}, [%4];"
        : "=r"(r[0]), "=r"(r[1]), "=r"(r[2]), "=r"(r[3]) : "r"(addr));
}
__device__ __forceinline__ void mma16(float* c, const uint32_t* a, uint32_t b0, uint32_t b1) {
    asm volatile("mma.sync.aligned.m16n8k16.row.col.f32.bf16.bf16.f32 "
        "{%0,%1,%2,%3}, {%4,%5,%6,%7}, {%8,%9}, {%0,%1,%2,%3};"
        : "+f"(c[0]), "+f"(c[1]), "+f"(c[2]), "+f"(c[3])
        : "r"(a[0]), "r"(a[1]), "r"(a[2]), "r"(a[3]), "r"(b0), "r"(b1));
}

// ---------------- prep: bf16 convert + sq norms + init ----------------
__global__ void prep_k(const float* __restrict__ emb) {
    if (blockIdx.x == 0 && threadIdx.x == 0) { g_sum = 0.0; g_cnt = 0; }
    int gw   = (blockIdx.x * blockDim.x + threadIdx.x) >> 5;
    int lane = threadIdx.x & 31;
    if (gw >= Nn) return;
    const float4* p = (const float4*)(emb + (size_t)gw * Dd);
    __nv_bfloat162* ph = (__nv_bfloat162*)(g_hi + (size_t)gw * Dd);
    float s = 0.f;
    #pragma unroll
    for (int q = 0; q < 2; q++) {
        int e = lane + q * 32;
        float4 v = p[e];
        ph[2*e]   = __nv_bfloat162(__float2bfloat16_rn(v.x), __float2bfloat16_rn(v.y));
        ph[2*e+1] = __nv_bfloat162(__float2bfloat16_rn(v.z), __float2bfloat16_rn(v.w));
        s += v.x * v.x + v.y * v.y + v.z * v.z + v.w * v.w;
    }
    #pragma unroll
    for (int o = 16; o; o >>= 1) s += __shfl_xor_sync(0xffffffffu, s, o);
    if (!lane) {
        g_sqn[gw] = s;
        g_bp[gw] = 0ull;
        g_bn[gw] = ~0ull;
    }
}

// ---------------- chunk loader: gmem -> padded row-major smem via cp.async ----------------
__device__ __forceinline__ void prefetch(uint32_t stg32, int i0, int j0, int kk, int tid) {
    #pragma unroll
    for (int t = 0; t < 8; t++) {
        int u    = tid + t * 256;          // 0..2047
        int tile = u >> 10;                // 0:A 1:B
        int w    = u & 1023;
        int row  = w >> 3;                 // 0..127
        int k4   = w & 7;                  // 0..7 (16B = 8 bf16 each)
        uint32_t dst = stg32 + tile * TILE_B + row * RB + k4 * 16;
        int base = (tile == 0 ? i0 : j0) + row;
        cpa16(dst, g_hi + (size_t)base * Dd + kk + k4 * 8);
    }
}

// ---------------- fused bf16 distance GEMM + bidirectional hardest mining ----------------
__global__ __launch_bounds__(256, 2)
void mine_k(const int* __restrict__ labels, const int* __restrict__ sbj) {
    extern __shared__ __align__(16) char sb[];
    const uint32_t sb32 = smem_u32(sb);

    const int tid  = threadIdx.x;
    const int wid  = tid >> 5;
    const int lane = tid & 31;
    const int gr   = lane >> 2;     // 0..7
    const int gc   = lane & 3;      // 0..3
    const int wy   = wid >> 2;      // 0..1  (M)
    const int wx   = wid & 3;       // 0..3  (N)

    const uint32_t lrow = lane & 15, khalf = lane >> 4;
    const uint32_t aoff = (wy * 64 + lrow) * RB + khalf * 16;
    const uint32_t boff = TILE_B + (wx * 32 + lrow) * RB + khalf * 16;

    int*   s_labi = (int*)  (sb + META);
    int*   s_sbji = (int*)  (sb + META + 512);
    float* s_sqi  = (float*)(sb + META + 1024);
    int*   s_labj = (int*)  (sb + META + 1536);
    int*   s_sbjj = (int*)  (sb + META + 2048);
    float* s_sqj  = (float*)(sb + META + 2560);

    for (int u = blockIdx.x; u < NTRI; u += GRID_MINE) {
        int ta = (int)((129.0 - sqrt(129.0 * 129.0 - 8.0 * (double)u)) * 0.5);
        while ((ta + 1) * NT - ((ta + 1) * ta) / 2 <= u) ta++;
        while (ta * NT - (ta * (ta - 1)) / 2 > u) ta--;
        const int tb = ta + (u - (ta * NT - (ta * (ta - 1)) / 2));
        const int i0 = ta * TM;
        const int j0 = tb * TN;
        const bool diag = (ta == tb);

        __syncthreads();   // previous epilogue done reading meta
        if (tid < 128) {
            s_labi[tid] = labels[i0 + tid];
            s_sbji[tid] = sbj[i0 + tid];
            s_sqi[tid]  = g_sqn[i0 + tid];
            s_labj[tid] = labels[j0 + tid];
            s_sbjj[tid] = sbj[j0 + tid];
            s_sqj[tid]  = g_sqn[j0 + tid];
        }

        prefetch(sb32,       i0, j0,  0, tid); cpa_commit();
        prefetch(sb32 + STG, i0, j0, 64, tid); cpa_commit();

        float acc[4][4][4];
        #pragma unroll
        for (int mt = 0; mt < 4; mt++)
            #pragma unroll
            for (int nt = 0; nt < 4; nt++)
                #pragma unroll
                for (int q = 0; q < 4; q++) acc[mt][nt][q] = 0.f;

        for (int c = 0; c < NCH; c++) {
            const int st = c & 1;
            if (c < NCH - 1) cpa_wait1(); else cpa_wait0();
            __syncthreads();

            const uint32_t stb = sb32 + st * STG;
            #pragma unroll
            for (int ks = 0; ks < 4; ks++) {
                const uint32_t kb = ks * 32;          // 16 bf16 = 32B
                uint32_t B0[4], B1[4];
                ldsm4(B0, stb + boff + kb);               // n-tiles 0,1
                ldsm4(B1, stb + boff + 16 * RB + kb);     // n-tiles 2,3
                #pragma unroll
                for (int mt = 0; mt < 4; mt++) {
                    uint32_t ah[4];
                    ldsm4(ah, stb + aoff + mt * 16 * RB + kb);
                    mma16(acc[mt][0], ah, B0[0], B0[2]);
                    mma16(acc[mt][1], ah, B0[1], B0[3]);
                    mma16(acc[mt][2], ah, B1[0], B1[2]);
                    mma16(acc[mt][3], ah, B1[1], B1[3]);
                }
            }
            __syncthreads();
            if (c + 2 < NCH) {
                prefetch(sb32 + st * STG, i0, j0, (c + 2) * 64, tid);
                cpa_commit();
            }
        }

        // ---------- per-thread attribute caches ----------
        float sqjv[8]; int labj[8], sbjj[8], jg[8];      // cols: q = nt*2+e
        #pragma unroll
        for (int q = 0; q < 8; q++) {
            int cl = wx * 32 + (q >> 1) * 8 + 2 * gc + (q & 1);
            sqjv[q] = s_sqj[cl]; labj[q] = s_labj[cl]; sbjj[q] = s_sbjj[cl];
            jg[q] = j0 + cl;
        }
        float sqiv[8]; int labi[8], sbji[8], igr[8];     // rows: r = mt*2+h
        #pragma unroll
        for (int r = 0; r < 8; r++) {
            int rl = wy * 64 + (r >> 1) * 16 + gr + (r & 1) * 8;
            sqiv[r] = s_sqi[rl]; labi[r] = s_labi[rl]; sbji[r] = s_sbji[rl];
            igr[r] = i0 + rl;
        }

        // ---------- row mining ----------
        #pragma unroll
        for (int r = 0; r < 8; r++) {
            float bpd = -1.f;    int bpi = -1;
            float bnd = 3.4e38f; int bni = -1;
            #pragma unroll
            for (int q = 0; q < 8; q++) {
                float d2 = fmaxf(fmaf(-2.f, acc[r >> 1][q >> 1][(r & 1) * 2 + (q & 1)],
                                      sqiv[r] + sqjv[q]), 0.f);
                if (sbjj[q] == sbji[r]) {
                    if (labj[q] == labi[r]) {
                        if (jg[q] != igr[r] && d2 > bpd) { bpd = d2; bpi = jg[q]; }
                    } else {
                        if (d2 < bnd) { bnd = d2; bni = jg[q]; }
                    }
                }
            }
            #pragma unroll
            for (int o = 1; o < 4; o <<= 1) {
                float od = __shfl_xor_sync(0xffffffffu, bpd, o);
                int   oi = __shfl_xor_sync(0xffffffffu, bpi, o);
                if (oi >= 0 && (bpi < 0 || od > bpd || (od == bpd && oi < bpi))) { bpd = od; bpi = oi; }
                od = __shfl_xor_sync(0xffffffffu, bnd, o);
                oi = __shfl_xor_sync(0xffffffffu, bni, o);
                if (oi >= 0 && (bni < 0 || od < bnd || (od == bnd && oi < bni))) { bnd = od; bni = oi; }
            }
            if (gc == 0) {
                if (bpi >= 0)
                    atomicMax(&g_bp[igr[r]], ((unsigned long long)__float_as_uint(bpd) << 32) |
                                             (unsigned long long)(~(unsigned)bpi));
                if (bni >= 0)
                    atomicMin(&g_bn[igr[r]], ((unsigned long long)__float_as_uint(bnd) << 32) |
                                             (unsigned long long)(unsigned)bni);
            }
        }

        // ---------- column mining (transpose view; skip on diagonal tiles) ----------
        if (!diag) {
            #pragma unroll
            for (int q = 0; q < 8; q++) {
                float bpd = -1.f;    int bpi = -1;
                float bnd = 3.4e38f; int bni = -1;
                #pragma unroll
                for (int r = 0; r < 8; r++) {
                    float d2 = fmaxf(fmaf(-2.f, acc[r >> 1][q >> 1][(r & 1) * 2 + (q & 1)],
                                          sqiv[r] + sqjv[q]), 0.f);
                    if (sbji[r] == sbjj[q]) {
                        if (labi[r] == labj[q]) {
                            if (d2 > bpd) { bpd = d2; bpi = igr[r]; }
                        } else {
                            if (d2 < bnd) { bnd = d2; bni = igr[r]; }
                        }
                    }
                }
                #pragma unroll
                for (int o = 4; o < 32; o <<= 1) {
                    float od = __shfl_xor_sync(0xffffffffu, bpd, o);
                    int   oi = __shfl_xor_sync(0xffffffffu, bpi, o);
                    if (oi >= 0 && (bpi < 0 || od > bpd || (od == bpd && oi < bpi))) { bpd = od; bpi = oi; }
                    od = __shfl_xor_sync(0xffffffffu, bnd, o);
                    oi = __shfl_xor_sync(0xffffffffu, bni, o);
                    if (oi >= 0 && (bni < 0 || od < bnd || (od == bnd && oi < bni))) { bnd = od; bni = oi; }
                }
                if (gr == 0) {
                    if (bpi >= 0)
                        atomicMax(&g_bp[jg[q]], ((unsigned long long)__float_as_uint(bpd) << 32) |
                                                (unsigned long long)(~(unsigned)bpi));
                    if (bni >= 0)
                        atomicMin(&g_bn[jg[q]], ((unsigned long long)__float_as_uint(bnd) << 32) |
                                                (unsigned long long)(unsigned)bni);
                }
            }
        }
    }
}

// ---------------- per-row triplet loss (exact fp32, +EPS) fused with reduction ----------------
__global__ void loss_k(const float* __restrict__ emb) {
    int gw   = (blockIdx.x * blockDim.x + threadIdx.x) >> 5;
    int lane = threadIdx.x & 31;
    if (gw >= Nn) return;
    unsigned long long pp = g_bp[gw], pn = g_bn[gw];
    int p = (pp == 0ull)  ? -1 : (int)(~(unsigned)(pp & 0xFFFFFFFFull));
    int q = (pn == ~0ull) ? -1 : (int)(unsigned)(pn & 0xFFFFFFFFull);
    bool valid = (p >= 0) && (q >= 0);
    float per = 0.f;
    if (valid) {
        const float4* ei = (const float4*)(emb + (size_t)gw * Dd);
        const float4* ep = (const float4*)(emb + (size_t)p  * Dd);
        const float4* en = (const float4*)(emb + (size_t)q  * Dd);
        float sp = 0.f, sn = 0.f;
        const float eps = 1e-6f;
        #pragma unroll
        for (int t = 0; t < 2; t++) {
            float4 a = ei[lane + t * 32], b = ep[lane + t * 32], c = en[lane + t * 32];
            float d;
            d = a.x - b.x + eps; sp += d * d;
            d = a.y - b.y + eps; sp += d * d;
            d = a.z - b.z + eps; sp += d * d;
            d = a.w - b.w + eps; sp += d * d;
            d = a.x - c.x + eps; sn += d * d;
            d = a.y - c.y + eps; sn += d * d;
            d = a.z - c.z + eps; sn += d * d;
            d = a.w - c.w + eps; sn += d * d;
        }
        #pragma unroll
        for (int o = 16; o; o >>= 1) {
            sp += __shfl_xor_sync(0xffffffffu, sp, o);
            sn += __shfl_xor_sync(0xffffffffu, sn, o);
        }
        per = fmaxf(sqrtf(sp) - sqrtf(sn) + 1.0f, 0.f);
    }
    if (!lane && valid) {
        atomicAdd(&g_sum, (double)per);
        atomicAdd(&g_cnt, 1);
    }
}

// ---------------- finalize ----------------
__global__ void final_k(float* __restrict__ out) {
    int cnt = g_cnt > 1 ? g_cnt : 1;
    out[0] = (float)(g_sum / (double)cnt);
}

extern "C" void kernel_launch(void* const* d_in, const int* in_sizes, int n_in,
                              void* d_out, int out_size) {
    const float* emb    = (const float*)d_in[0];
    const int*   labels = (const int*)d_in[1];
    const int*   sbjv   = (const int*)d_in[2];
    float* out = (float*)d_out;

    cudaFuncSetAttribute(mine_k, cudaFuncAttributeMaxDynamicSharedMemorySize, SMEM_DYN);

    prep_k<<<Nn / 8, 256>>>(emb);
    mine_k<<<GRID_MINE, 256, SMEM_DYN>>>(labels, sbjv);
    loss_k<<<Nn / 8, 256>>>(emb);
    final_k<<<1, 1>>>(out);
}

// round 9
// speedup vs baseline: 25.6024x; 2.8819x over previous
#include <cuda_runtime.h>
#include <cuda_bf16.h>
#include <cstdint>

#define Nn 8192
#define Dd 256
#define NSUB 16
#define PROW 1024             // padded rows per subject (counts ~512, huge margin)
#define PTOT (NSUB*PROW)      // 16384
#define MAXT 600
#define GRID_MINE 288
#define NCH 4                 // K chunks of 64 elements

#define RB     144            // smem row stride bytes (LDSM conflict-free)
#define TILE_B 18432          // 128 rows * 144B
#define STG    36864          // bytes per pipeline stage (A + B)
#define META   73728
#define SMEM_DYN (META + 8*128*4)

__device__ __align__(256) __nv_bfloat16 g_pe[PTOT*Dd];
__device__ float g_psq[PTOT];
__device__ int   g_plab[PTOT];
__device__ int   g_porg[PTOT];
__device__ int   g_pidx[PTOT];
__device__ int   g_tiles[MAXT];
__device__ int   g_ntiles;
__device__ unsigned long long g_bp[Nn+1];
__device__ unsigned long long g_bn[Nn+1];
__device__ double g_sum;
__device__ int    g_cnt;

// ---------------- PTX helpers ----------------
__device__ __forceinline__ uint32_t smem_u32(const void* p) {
    uint32_t a;
    asm("{ .reg .u64 t; cvta.to.shared.u64 t, %1; cvt.u32.u64 %0, t; }" : "=r"(a) : "l"(p));
    return a;
}
__device__ __forceinline__ void cpa16(uint32_t dst, const __nv_bfloat16* src) {
    asm volatile("cp.async.cg.shared.global [%0], [%1], 16;" :: "r"(dst), "l"(src));
}
__device__ __forceinline__ void cpa_commit() { asm volatile("cp.async.commit_group;" ::: "memory"); }
__device__ __forceinline__ void cpa_wait1()  { asm volatile("cp.async.wait_group 1;" ::: "memory"); }
__device__ __forceinline__ void cpa_wait0()  { asm volatile("cp.async.wait_group 0;" ::: "memory"); }

__device__ __forceinline__ void ldsm4(uint32_t* r, uint32_t addr) {
    asm volatile("ldmatrix.sync.aligned.m8n8.x4.shared.b16 {%0,%1,%2,%3}, [%4];"
        : "=r"(r[0]), "=r"(r[1]), "=r"(r[2]), "=r"(r[3]) : "r"(addr));
}
__device__ __forceinline__ void mma16(float* c, const uint32_t* a, uint32_t b0, uint32_t b1) {
    asm volatile("mma.sync.aligned.m16n8k16.row.col.f32.bf16.bf16.f32 "
        "{%0,%1,%2,%3}, {%4,%5,%6,%7}, {%8,%9}, {%0,%1,%2,%3};"
        : "+f"(c[0]), "+f"(c[1]), "+f"(c[2]), "+f"(c[3])
        : "r"(a[0]), "r"(a[1]), "r"(a[2]), "r"(a[3]), "r"(b0), "r"(b1));
}

// ---------------- s1: subject counts -> triangular tile list ----------------
__global__ void s1_k(const int* __restrict__ sbj) {
    __shared__ int cnt[NSUB];
    int tid = threadIdx.x;
    if (tid == 0) { g_sum = 0.0; g_cnt = 0; }
    if (tid < NSUB) cnt[tid] = 0;
    __syncthreads();
    for (int i = tid; i < Nn; i += 256) atomicAdd(&cnt[sbj[i]], 1);
    __syncthreads();
    if (tid == 0) {
        int n = 0;
        for (int s = 0; s < NSUB; s++) {
            int nt = (cnt[s] + 127) >> 7;
            for (int a = 0; a < nt; a++)
                for (int b = a; b < nt; b++)
                    g_tiles[n++] = (s << 8) | (a << 4) | b;
        }
        g_ntiles = n;
    }
}

// ---------------- s2: stable compaction of row indices per subject ----------------
__global__ void s2_k(const int* __restrict__ sbj) {
    const int s = blockIdx.x, tid = threadIdx.x;
    __shared__ int wsum[8];
    __shared__ int base;
    for (int t = tid; t < PROW; t += 256) g_pidx[s * PROW + t] = -1;
    if (tid == 0) base = 0;
    __syncthreads();
    const int wid = tid >> 5, lane = tid & 31;
    for (int b = 0; b < Nn / 256; b++) {
        int i = b * 256 + tid;
        bool pred = (sbj[i] == s);
        unsigned m = __ballot_sync(0xffffffffu, pred);
        if (lane == 0) wsum[wid] = __popc(m);
        __syncthreads();
        int woff = 0, tot = 0;
        #pragma unroll
        for (int w = 0; w < 8; w++) { if (w < wid) woff += wsum[w]; tot += wsum[w]; }
        if (pred)
            g_pidx[s * PROW + base + woff + __popc(m & ((1u << lane) - 1u))] = i;
        __syncthreads();
        if (tid == 0) base += tot;
        __syncthreads();
    }
}

// ---------------- s3: gather rows (bf16), sq norms, meta, best-init ----------------
__global__ void s3_k(const float* __restrict__ emb, const int* __restrict__ labels) {
    int gw   = (blockIdx.x * blockDim.x + threadIdx.x) >> 5;
    int lane = threadIdx.x & 31;
    if (gw >= PTOT) return;
    if (gw <= Nn && lane == 0) { g_bp[gw] = 0ull; g_bn[gw] = ~0ull; }
    int i = g_pidx[gw];
    __nv_bfloat162* ph = (__nv_bfloat162*)(g_pe + (size_t)gw * Dd);
    if (i >= 0) {
        const float4* p = (const float4*)(emb + (size_t)i * Dd);
        float ssum = 0.f;
        #pragma unroll
        for (int q2 = 0; q2 < 2; q2++) {
            int e = lane + q2 * 32;
            float4 v = p[e];
            ph[2*e]   = __nv_bfloat162(__float2bfloat16_rn(v.x), __float2bfloat16_rn(v.y));
            ph[2*e+1] = __nv_bfloat162(__float2bfloat16_rn(v.z), __float2bfloat16_rn(v.w));
            ssum += v.x * v.x + v.y * v.y + v.z * v.z + v.w * v.w;
        }
        #pragma unroll
        for (int o = 16; o; o >>= 1) ssum += __shfl_xor_sync(0xffffffffu, ssum, o);
        if (!lane) { g_psq[gw] = ssum; g_plab[gw] = labels[i]; g_porg[gw] = i; }
    } else {
        __nv_bfloat162 z = __nv_bfloat162(__float2bfloat16_rn(0.f), __float2bfloat16_rn(0.f));
        #pragma unroll
        for (int q2 = 0; q2 < 2; q2++) {
            int e = lane + q2 * 32;
            ph[2*e] = z; ph[2*e+1] = z;
        }
        if (!lane) { g_psq[gw] = 0.f; g_plab[gw] = -2; g_porg[gw] = Nn; }
    }
}

// ---------------- chunk loader: permuted gmem -> padded smem via cp.async ----------------
__device__ __forceinline__ void prefetch(uint32_t stg32, int i0, int j0, int kk, int tid) {
    #pragma unroll
    for (int t = 0; t < 8; t++) {
        int u    = tid + t * 256;          // 0..2047
        int tile = u >> 10;                // 0:A 1:B
        int w    = u & 1023;
        int row  = w >> 3;                 // 0..127
        int k4   = w & 7;                  // 0..7
        uint32_t dst = stg32 + tile * TILE_B + row * RB + k4 * 16;
        int base = (tile == 0 ? i0 : j0) + row;
        cpa16(dst, g_pe + (size_t)base * Dd + kk + k4 * 8);
    }
}

// ---------------- fused within-subject distance GEMM + bidirectional mining ----------------
__global__ __launch_bounds__(256, 2)
void mine_k() {
    extern __shared__ __align__(16) char sb[];
    const uint32_t sb32 = smem_u32(sb);

    const int tid  = threadIdx.x;
    const int wid  = tid >> 5;
    const int lane = tid & 31;
    const int gr   = lane >> 2;     // 0..7
    const int gc   = lane & 3;      // 0..3
    const int wy   = wid >> 2;      // 0..1  (M)
    const int wx   = wid & 3;       // 0..3  (N)

    const uint32_t lrow = lane & 15, khalf = lane >> 4;
    const uint32_t aoff = (wy * 64 + lrow) * RB + khalf * 16;
    const uint32_t boff = TILE_B + (wx * 32 + lrow) * RB + khalf * 16;

    int*   s_labi = (int*)  (sb + META);
    float* s_sqi  = (float*)(sb + META + 512);
    int*   s_orgi = (int*)  (sb + META + 1024);
    int*   s_labj = (int*)  (sb + META + 1536);
    float* s_sqj  = (float*)(sb + META + 2048);
    int*   s_orgj = (int*)  (sb + META + 2560);

    const int ntiles = g_ntiles;
    for (int u = blockIdx.x; u < ntiles; u += GRID_MINE) {
        const int tdesc = g_tiles[u];
        const int s  = tdesc >> 8;
        const int ti = (tdesc >> 4) & 15;
        const int tj = tdesc & 15;
        const int i0 = s * PROW + ti * 128;
        const int j0 = s * PROW + tj * 128;
        const bool diag = (ti == tj);

        __syncthreads();   // previous epilogue done reading meta
        if (tid < 128) {
            s_labi[tid] = g_plab[i0 + tid];
            s_sqi[tid]  = g_psq[i0 + tid];
            s_orgi[tid] = g_porg[i0 + tid];
            s_labj[tid] = g_plab[j0 + tid];
            s_sqj[tid]  = g_psq[j0 + tid];
            s_orgj[tid] = g_porg[j0 + tid];
        }

        prefetch(sb32,       i0, j0,  0, tid); cpa_commit();
        prefetch(sb32 + STG, i0, j0, 64, tid); cpa_commit();

        float acc[4][4][4];
        #pragma unroll
        for (int mt = 0; mt < 4; mt++)
            #pragma unroll
            for (int nt = 0; nt < 4; nt++)
                #pragma unroll
                for (int q = 0; q < 4; q++) acc[mt][nt][q] = 0.f;

        for (int c = 0; c < NCH; c++) {
            const int st = c & 1;
            if (c < NCH - 1) cpa_wait1(); else cpa_wait0();
            __syncthreads();

            const uint32_t stb = sb32 + st * STG;
            #pragma unroll
            for (int ks = 0; ks < 4; ks++) {
                const uint32_t kb = ks * 32;
                uint32_t B0[4], B1[4];
                ldsm4(B0, stb + boff + kb);
                ldsm4(B1, stb + boff + 16 * RB + kb);
                #pragma unroll
                for (int mt = 0; mt < 4; mt++) {
                    uint32_t ah[4];
                    ldsm4(ah, stb + aoff + mt * 16 * RB + kb);
                    mma16(acc[mt][0], ah, B0[0], B0[2]);
                    mma16(acc[mt][1], ah, B0[1], B0[3]);
                    mma16(acc[mt][2], ah, B1[0], B1[2]);
                    mma16(acc[mt][3], ah, B1[1], B1[3]);
                }
            }
            __syncthreads();
            if (c + 2 < NCH) {
                prefetch(sb32 + st * STG, i0, j0, (c + 2) * 64, tid);
                cpa_commit();
            }
        }

        // ---------- attribute caches ----------
        float sqjv[8]; int labj[8], jg[8];
        #pragma unroll
        for (int q = 0; q < 8; q++) {
            int cl = wx * 32 + (q >> 1) * 8 + 2 * gc + (q & 1);
            sqjv[q] = s_sqj[cl]; labj[q] = s_labj[cl]; jg[q] = s_orgj[cl];
        }
        float sqiv[8]; int labi[8], igr[8];
        #pragma unroll
        for (int r = 0; r < 8; r++) {
            int rl = wy * 64 + (r >> 1) * 16 + gr + (r & 1) * 8;
            sqiv[r] = s_sqi[rl]; labi[r] = s_labi[rl]; igr[r] = s_orgi[rl];
        }

        // ---------- transform acc -> clamped d^2 (once) ----------
        #pragma unroll
        for (int mt = 0; mt < 4; mt++)
            #pragma unroll
            for (int nt = 0; nt < 4; nt++)
                #pragma unroll
                for (int q = 0; q < 4; q++)
                    acc[mt][nt][q] = fmaxf(fmaf(-2.f, acc[mt][nt][q],
                        sqiv[mt * 2 + (q >> 1)] + sqjv[nt * 2 + (q & 1)]), 0.f);

        // ---------- row mining ----------
        #pragma unroll
        for (int r = 0; r < 8; r++) {
            float bpd = -1.f;    int bpi = -1;
            float bnd = 3.4e38f; int bni = -1;
            const bool ra = (labi[r] >= 0);
            #pragma unroll
            for (int q = 0; q < 8; q++) {
                float d2 = acc[r >> 1][q >> 1][(r & 1) * 2 + (q & 1)];
                if (labj[q] == labi[r]) {
                    if (jg[q] != igr[r] && d2 > bpd) { bpd = d2; bpi = jg[q]; }
                } else if (ra && labj[q] >= 0) {
                    if (d2 < bnd) { bnd = d2; bni = jg[q]; }
                }
            }
            #pragma unroll
            for (int o = 1; o < 4; o <<= 1) {
                float od = __shfl_xor_sync(0xffffffffu, bpd, o);
                int   oi = __shfl_xor_sync(0xffffffffu, bpi, o);
                if (oi >= 0 && (bpi < 0 || od > bpd || (od == bpd && oi < bpi))) { bpd = od; bpi = oi; }
                od = __shfl_xor_sync(0xffffffffu, bnd, o);
                oi = __shfl_xor_sync(0xffffffffu, bni, o);
                if (oi >= 0 && (bni < 0 || od < bnd || (od == bnd && oi < bni))) { bnd = od; bni = oi; }
            }
            if (gc == 0) {
                if (bpi >= 0)
                    atomicMax(&g_bp[igr[r]], ((unsigned long long)__float_as_uint(bpd) << 32) |
                                             (unsigned long long)(~(unsigned)bpi));
                if (bni >= 0)
                    atomicMin(&g_bn[igr[r]], ((unsigned long long)__float_as_uint(bnd) << 32) |
                                             (unsigned long long)(unsigned)bni);
            }
        }

        // ---------- column mining (transpose view; skip diagonal) ----------
        if (!diag) {
            #pragma unroll
            for (int q = 0; q < 8; q++) {
                float bpd = -1.f;    int bpi = -1;
                float bnd = 3.4e38f; int bni = -1;
                const bool ca = (labj[q] >= 0);
                #pragma unroll
                for (int r = 0; r < 8; r++) {
                    float d2 = acc[r >> 1][q >> 1][(r & 1) * 2 + (q & 1)];
                    if (labi[r] == labj[q]) {
                        if (igr[r] != jg[q] && d2 > bpd) { bpd = d2; bpi = igr[r]; }
                    } else if (ca && labi[r] >= 0) {
                        if (d2 < bnd) { bnd = d2; bni = igr[r]; }
                    }
                }
                #pragma unroll
                for (int o = 4; o < 32; o <<= 1) {
                    float od = __shfl_xor_sync(0xffffffffu, bpd, o);
                    int   oi = __shfl_xor_sync(0xffffffffu, bpi, o);
                    if (oi >= 0 && (bpi < 0 || od > bpd || (od == bpd && oi < bpi))) { bpd = od; bpi = oi; }
                    od = __shfl_xor_sync(0xffffffffu, bnd, o);
                    oi = __shfl_xor_sync(0xffffffffu, bni, o);
                    if (oi >= 0 && (bni < 0 || od < bnd || (od == bnd && oi < bni))) { bnd = od; bni = oi; }
                }
                if (gr == 0) {
                    if (bpi >= 0)
                        atomicMax(&g_bp[jg[q]], ((unsigned long long)__float_as_uint(bpd) << 32) |
                                                (unsigned long long)(~(unsigned)bpi));
                    if (bni >= 0)
                        atomicMin(&g_bn[jg[q]], ((unsigned long long)__float_as_uint(bnd) << 32) |
                                                (unsigned long long)(unsigned)bni);
                }
            }
        }
    }
}

// ---------------- per-row triplet loss (exact fp32, +EPS) fused with reduction ----------------
__global__ void loss_k(const float* __restrict__ emb) {
    int gw   = (blockIdx.x * blockDim.x + threadIdx.x) >> 5;
    int lane = threadIdx.x & 31;
    if (gw >= Nn) return;
    unsigned long long pp = g_bp[gw], pn = g_bn[gw];
    int p = (pp == 0ull)  ? -1 : (int)(~(unsigned)(pp & 0xFFFFFFFFull));
    int q = (pn == ~0ull) ? -1 : (int)(unsigned)(pn & 0xFFFFFFFFull);
    bool valid = (p >= 0) && (q >= 0);
    float per = 0.f;
    if (valid) {
        const float4* ei = (const float4*)(emb + (size_t)gw * Dd);
        const float4* ep = (const float4*)(emb + (size_t)p  * Dd);
        const float4* en = (const float4*)(emb + (size_t)q  * Dd);
        float sp = 0.f, sn = 0.f;
        const float eps = 1e-6f;
        #pragma unroll
        for (int t = 0; t < 2; t++) {
            float4 a = ei[lane + t * 32], b = ep[lane + t * 32], c = en[lane + t * 32];
            float d;
            d = a.x - b.x + eps; sp += d * d;
            d = a.y - b.y + eps; sp += d * d;
            d = a.z - b.z + eps; sp += d * d;
            d = a.w - b.w + eps; sp += d * d;
            d = a.x - c.x + eps; sn += d * d;
            d = a.y - c.y + eps; sn += d * d;
            d = a.z - c.z + eps; sn += d * d;
            d = a.w - c.w + eps; sn += d * d;
        }
        #pragma unroll
        for (int o = 16; o; o >>= 1) {
            sp += __shfl_xor_sync(0xffffffffu, sp, o);
            sn += __shfl_xor_sync(0xffffffffu, sn, o);
        }
        per = fmaxf(sqrtf(sp) - sqrtf(sn) + 1.0f, 0.f);
    }
    if (!lane && valid) {
        atomicAdd(&g_sum, (double)per);
        atomicAdd(&g_cnt, 1);
    }
}

// ---------------- finalize ----------------
__global__ void final_k(float* __restrict__ out) {
    int cnt = g_cnt > 1 ? g_cnt : 1;
    out[0] = (float)(g_sum / (double)cnt);
}

extern "C" void kernel_launch(void* const* d_in, const int* in_sizes, int n_in,
                              void* d_out, int out_size) {
    const float* emb    = (const float*)d_in[0];
    const int*   labels = (const int*)d_in[1];
    const int*   sbjv   = (const int*)d_in[2];
    float* out = (float*)d_out;

    cudaFuncSetAttribute(mine_k, cudaFuncAttributeMaxDynamicSharedMemorySize, SMEM_DYN);

    s1_k<<<1, 256>>>(sbjv);
    s2_k<<<NSUB, 256>>>(sbjv);
    s3_k<<<PTOT / 8, 256>>>(emb, labels);
    mine_k<<<GRID_MINE, 256, SMEM_DYN>>>();
    loss_k<<<Nn / 8, 256>>>(emb);
    final_k<<<1, 1>>>(out);
}

// round 10
// speedup vs baseline: 36.0843x; 1.4094x over previous
#include <cuda_runtime.h>
#include <cuda_bf16.h>
#include <cstdint>

#define Nn 8192
#define Dd 256
#define NSUB 16
#define PROW 1024             // padded rows per subject
#define PTOT (NSUB*PROW)      // 16384
#define TSLOT 64              // tile-desc slots per subject
#define GRID_MINE 288
#define NCH 4                 // K chunks of 64 elements

#define RB     144            // smem row stride bytes (LDSM conflict-free)
#define TILE_B 18432          // 128 rows * 144B
#define STG    36864          // bytes per pipeline stage (A + B)
#define META   73728
#define SMEM_DYN (META + 8*128*4)

__device__ __align__(256) __nv_bfloat16 g_pe[PTOT*Dd];
__device__ float g_psq[PTOT];
__device__ int   g_plab[PTOT];
__device__ int   g_porg[PTOT];
__device__ int   g_pidx[PTOT];
__device__ int   g_tiles[NSUB*TSLOT];
__device__ int   g_tpc[NSUB];
__device__ unsigned long long g_bp[Nn+1];
__device__ unsigned long long g_bn[Nn+1];

// ---------------- PTX helpers ----------------
__device__ __forceinline__ uint32_t smem_u32(const void* p) {
    uint32_t a;
    asm("{ .reg .u64 t; cvta.to.shared.u64 t, %1; cvt.u32.u64 %0, t; }" : "=r"(a) : "l"(p));
    return a;
}
__device__ __forceinline__ void cpa16(uint32_t dst, const __nv_bfloat16* src) {
    asm volatile("cp.async.cg.shared.global [%0], [%1], 16;" :: "r"(dst), "l"(src));
}
__device__ __forceinline__ void cpa_commit() { asm volatile("cp.async.commit_group;" ::: "memory"); }
__device__ __forceinline__ void cpa_wait1()  { asm volatile("cp.async.wait_group 1;" ::: "memory"); }
__device__ __forceinline__ void cpa_wait0()  { asm volatile("cp.async.wait_group 0;" ::: "memory"); }

__device__ __forceinline__ void ldsm4(uint32_t* r, uint32_t addr) {
    asm volatile("ldmatrix.sync.aligned.m8n8.x4.shared.b16 {%0,%1,%2,%3}, [%4];"
        : "=r"(r[0]), "=r"(r[1]), "=r"(r[2]), "=r"(r[3]) : "r"(addr));
}
__device__ __forceinline__ void mma16(float* c, const uint32_t* a, uint32_t b0, uint32_t b1) {
    asm volatile("mma.sync.aligned.m16n8k16.row.col.f32.bf16.bf16.f32 "
        "{%0,%1,%2,%3}, {%4,%5,%6,%7}, {%8,%9}, {%0,%1,%2,%3};"
        : "+f"(c[0]), "+f"(c[1]), "+f"(c[2]), "+f"(c[3])
        : "r"(a[0]), "r"(a[1]), "r"(a[2]), "r"(a[3]), "r"(b0), "r"(b1));
}

// ---------------- k12: per-subject stable compaction + tile list ----------------
__global__ void k12_k(const int* __restrict__ sbj) {
    const int s = blockIdx.x, tid = threadIdx.x;
    __shared__ int wsum[8];
    __shared__ int base;
    for (int t = tid; t < PROW; t += 256) g_pidx[s * PROW + t] = -1;
    if (tid == 0) base = 0;
    __syncthreads();
    const int wid = tid >> 5, lane = tid & 31;
    for (int b = 0; b < Nn / 256; b++) {
        int i = b * 256 + tid;
        bool pred = (sbj[i] == s);
        unsigned m = __ballot_sync(0xffffffffu, pred);
        if (lane == 0) wsum[wid] = __popc(m);
        __syncthreads();
        int woff = 0, tot = 0;
        #pragma unroll
        for (int w = 0; w < 8; w++) { if (w < wid) woff += wsum[w]; tot += wsum[w]; }
        if (pred)
            g_pidx[s * PROW + base + woff + __popc(m & ((1u << lane) - 1u))] = i;
        __syncthreads();
        if (tid == 0) base += tot;
        __syncthreads();
    }
    if (tid == 0) {
        int nt = (base + 127) >> 7;
        int n = 0;
        for (int a = 0; a < nt; a++)
            for (int b = a; b < nt; b++)
                g_tiles[s * TSLOT + n++] = (s << 8) | (a << 4) | b;
        g_tpc[s] = n;
    }
}

// ---------------- s3: gather rows (bf16), sq norms, meta, best-init ----------------
__global__ void s3_k(const float* __restrict__ emb, const int* __restrict__ labels) {
    int gw   = (blockIdx.x * blockDim.x + threadIdx.x) >> 5;
    int lane = threadIdx.x & 31;
    if (gw >= PTOT) return;
    if (gw <= Nn && lane == 0) { g_bp[gw] = 0ull; g_bn[gw] = ~0ull; }
    int i = g_pidx[gw];
    __nv_bfloat162* ph = (__nv_bfloat162*)(g_pe + (size_t)gw * Dd);
    if (i >= 0) {
        const float4* p = (const float4*)(emb + (size_t)i * Dd);
        float ssum = 0.f;
        #pragma unroll
        for (int q2 = 0; q2 < 2; q2++) {
            int e = lane + q2 * 32;
            float4 v = p[e];
            ph[2*e]   = __nv_bfloat162(__float2bfloat16_rn(v.x), __float2bfloat16_rn(v.y));
            ph[2*e+1] = __nv_bfloat162(__float2bfloat16_rn(v.z), __float2bfloat16_rn(v.w));
            ssum += v.x * v.x + v.y * v.y + v.z * v.z + v.w * v.w;
        }
        #pragma unroll
        for (int o = 16; o; o >>= 1) ssum += __shfl_xor_sync(0xffffffffu, ssum, o);
        if (!lane) { g_psq[gw] = ssum; g_plab[gw] = labels[i]; g_porg[gw] = i; }
    } else {
        __nv_bfloat162 z = __nv_bfloat162(__float2bfloat16_rn(0.f), __float2bfloat16_rn(0.f));
        #pragma unroll
        for (int q2 = 0; q2 < 2; q2++) {
            int e = lane + q2 * 32;
            ph[2*e] = z; ph[2*e+1] = z;
        }
        if (!lane) { g_psq[gw] = 0.f; g_plab[gw] = -2; g_porg[gw] = Nn; }
    }
}

// ---------------- chunk loader (skips B tile for diagonal) ----------------
__device__ __forceinline__ void prefetch(uint32_t stg32, int i0, int j0, int kk,
                                         int tid, bool diag) {
    #pragma unroll
    for (int t = 0; t < 4; t++) {          // A tile
        int w   = tid + t * 256;           // 0..1023
        int row = w >> 3, k4 = w & 7;
        cpa16(stg32 + row * RB + k4 * 16,
              g_pe + (size_t)(i0 + row) * Dd + kk + k4 * 8);
    }
    if (!diag) {
        #pragma unroll
        for (int t = 0; t < 4; t++) {      // B tile
            int w   = tid + t * 256;
            int row = w >> 3, k4 = w & 7;
            cpa16(stg32 + TILE_B + row * RB + k4 * 16,
                  g_pe + (size_t)(j0 + row) * Dd + kk + k4 * 8);
        }
    }
}

// ---------------- fused within-subject distance GEMM + bidirectional mining ----------------
__global__ __launch_bounds__(256, 2)
void mine_k() {
    extern __shared__ __align__(16) char sb[];
    const uint32_t sb32 = smem_u32(sb);

    const int tid  = threadIdx.x;
    const int wid  = tid >> 5;
    const int lane = tid & 31;
    const int gr   = lane >> 2;
    const int gc   = lane & 3;
    const int wy   = wid >> 2;
    const int wx   = wid & 3;

    const uint32_t lrow = lane & 15, khalf = lane >> 4;
    const uint32_t aoff  = (wy * 64 + lrow) * RB + khalf * 16;
    const uint32_t boff0 = (wx * 32 + lrow) * RB + khalf * 16;

    int*   s_labi = (int*)  (sb + META);
    float* s_sqi  = (float*)(sb + META + 512);
    int*   s_orgi = (int*)  (sb + META + 1024);
    int*   s_labj = (int*)  (sb + META + 1536);
    float* s_sqj  = (float*)(sb + META + 2048);
    int*   s_orgj = (int*)  (sb + META + 2560);

    int off[NSUB + 1];
    off[0] = 0;
    #pragma unroll
    for (int s = 0; s < NSUB; s++) off[s + 1] = off[s] + g_tpc[s];
    const int total = off[NSUB];

    for (int u = blockIdx.x; u < total; u += GRID_MINE) {
        int s = 0;
        #pragma unroll
        for (int t = 0; t < NSUB; t++) if (u >= off[t + 1]) s = t + 1;
        const int tdesc = g_tiles[s * TSLOT + (u - off[s])];
        const int ti = (tdesc >> 4) & 15;
        const int tj = tdesc & 15;
        const int i0 = s * PROW + ti * 128;
        const int j0 = s * PROW + tj * 128;
        const bool diag = (ti == tj);
        const uint32_t btile = diag ? 0u : (uint32_t)TILE_B;

        __syncthreads();   // previous epilogue done reading meta
        if (tid < 128) {
            s_labi[tid] = g_plab[i0 + tid];
            s_sqi[tid]  = g_psq[i0 + tid];
            s_orgi[tid] = g_porg[i0 + tid];
            s_labj[tid] = g_plab[j0 + tid];
            s_sqj[tid]  = g_psq[j0 + tid];
            s_orgj[tid] = g_porg[j0 + tid];
        }

        prefetch(sb32,       i0, j0,  0, tid, diag); cpa_commit();
        prefetch(sb32 + STG, i0, j0, 64, tid, diag); cpa_commit();

        float acc[4][4][4];
        #pragma unroll
        for (int mt = 0; mt < 4; mt++)
            #pragma unroll
            for (int nt = 0; nt < 4; nt++)
                #pragma unroll
                for (int q = 0; q < 4; q++) acc[mt][nt][q] = 0.f;

        for (int c = 0; c < NCH; c++) {
            const int st = c & 1;
            if (c < NCH - 1) cpa_wait1(); else cpa_wait0();
            __syncthreads();

            const uint32_t stb = sb32 + st * STG;
            #pragma unroll
            for (int ks = 0; ks < 4; ks++) {
                const uint32_t kb = ks * 32;
                uint32_t B0[4], B1[4];
                ldsm4(B0, stb + btile + boff0 + kb);
                ldsm4(B1, stb + btile + boff0 + 16 * RB + kb);
                #pragma unroll
                for (int mt = 0; mt < 4; mt++) {
                    uint32_t ah[4];
                    ldsm4(ah, stb + aoff + mt * 16 * RB + kb);
                    mma16(acc[mt][0], ah, B0[0], B0[2]);
                    mma16(acc[mt][1], ah, B0[1], B0[3]);
                    mma16(acc[mt][2], ah, B1[0], B1[2]);
                    mma16(acc[mt][3], ah, B1[1], B1[3]);
                }
            }
            __syncthreads();
            if (c + 2 < NCH) {
                prefetch(sb32 + st * STG, i0, j0, (c + 2) * 64, tid, diag);
                cpa_commit();
            }
        }

        // ---------- attribute caches ----------
        float sqjv[8]; int labj[8], jg[8];
        #pragma unroll
        for (int q = 0; q < 8; q++) {
            int cl = wx * 32 + (q >> 1) * 8 + 2 * gc + (q & 1);
            sqjv[q] = s_sqj[cl]; labj[q] = s_labj[cl]; jg[q] = s_orgj[cl];
        }
        float sqiv[8]; int labi[8], igr[8];
        #pragma unroll
        for (int r = 0; r < 8; r++) {
            int rl = wy * 64 + (r >> 1) * 16 + gr + (r & 1) * 8;
            sqiv[r] = s_sqi[rl]; labi[r] = s_labi[rl]; igr[r] = s_orgi[rl];
        }

        // ---------- transform acc -> clamped d^2 ----------
        #pragma unroll
        for (int mt = 0; mt < 4; mt++)
            #pragma unroll
            for (int nt = 0; nt < 4; nt++)
                #pragma unroll
                for (int q = 0; q < 4; q++)
                    acc[mt][nt][q] = fmaxf(fmaf(-2.f, acc[mt][nt][q],
                        sqiv[mt * 2 + (q >> 1)] + sqjv[nt * 2 + (q & 1)]), 0.f);

        // ---------- row mining ----------
        #pragma unroll
        for (int r = 0; r < 8; r++) {
            float bpd = -1.f;    int bpi = -1;
            float bnd = 3.4e38f; int bni = -1;
            const bool ra = (labi[r] >= 0);
            #pragma unroll
            for (int q = 0; q < 8; q++) {
                float d2 = acc[r >> 1][q >> 1][(r & 1) * 2 + (q & 1)];
                if (labj[q] == labi[r]) {
                    if (jg[q] != igr[r] && d2 > bpd) { bpd = d2; bpi = jg[q]; }
                } else if (ra && labj[q] >= 0) {
                    if (d2 < bnd) { bnd = d2; bni = jg[q]; }
                }
            }
            #pragma unroll
            for (int o = 1; o < 4; o <<= 1) {
                float od = __shfl_xor_sync(0xffffffffu, bpd, o);
                int   oi = __shfl_xor_sync(0xffffffffu, bpi, o);
                if (oi >= 0 && (bpi < 0 || od > bpd || (od == bpd && oi < bpi))) { bpd = od; bpi = oi; }
                od = __shfl_xor_sync(0xffffffffu, bnd, o);
                oi = __shfl_xor_sync(0xffffffffu, bni, o);
                if (oi >= 0 && (bni < 0 || od < bnd || (od == bnd && oi < bni))) { bnd = od; bni = oi; }
            }
            if (gc == 0) {
                if (bpi >= 0)
                    atomicMax(&g_bp[igr[r]], ((unsigned long long)__float_as_uint(bpd) << 32) |
                                             (unsigned long long)(~(unsigned)bpi));
                if (bni >= 0)
                    atomicMin(&g_bn[igr[r]], ((unsigned long long)__float_as_uint(bnd) << 32) |
                                             (unsigned long long)(unsigned)bni);
            }
        }

        // ---------- column mining (transpose view; skip diagonal) ----------
        if (!diag) {
            #pragma unroll
            for (int q = 0; q < 8; q++) {
                float bpd = -1.f;    int bpi = -1;
                float bnd = 3.4e38f; int bni = -1;
                const bool ca = (labj[q] >= 0);
                #pragma unroll
                for (int r = 0; r < 8; r++) {
                    float d2 = acc[r >> 1][q >> 1][(r & 1) * 2 + (q & 1)];
                    if (labi[r] == labj[q]) {
                        if (igr[r] != jg[q] && d2 > bpd) { bpd = d2; bpi = igr[r]; }
                    } else if (ca && labi[r] >= 0) {
                        if (d2 < bnd) { bnd = d2; bni = igr[r]; }
                    }
                }
                #pragma unroll
                for (int o = 4; o < 32; o <<= 1) {
                    float od = __shfl_xor_sync(0xffffffffu, bpd, o);
                    int   oi = __shfl_xor_sync(0xffffffffu, bpi, o);
                    if (oi >= 0 && (bpi < 0 || od > bpd || (od == bpd && oi < bpi))) { bpd = od; bpi = oi; }
                    od = __shfl_xor_sync(0xffffffffu, bnd, o);
                    oi = __shfl_xor_sync(0xffffffffu, bni, o);
                    if (oi >= 0 && (bni < 0 || od < bnd || (od == bnd && oi < bni))) { bnd = od; bni = oi; }
                }
                if (gr == 0) {
                    if (bpi >= 0)
                        atomicMax(&g_bp[jg[q]], ((unsigned long long)__float_as_uint(bpd) << 32) |
                                                (unsigned long long)(~(unsigned)bpi));
                    if (bni >= 0)
                        atomicMin(&g_bn[jg[q]], ((unsigned long long)__float_as_uint(bnd) << 32) |
                                                (unsigned long long)(unsigned)bni);
                }
            }
        }
    }
}

// ---------------- loss from mined keys (single block, writes out) ----------------
__global__ void loss_k(float* __restrict__ out) {
    __shared__ float ssum[32];
    __shared__ int   scnt[32];
    const int tid = threadIdx.x;
    float acc = 0.f; int c = 0;
    for (int i = tid; i < Nn; i += 1024) {
        unsigned long long pp = g_bp[i], pn = g_bn[i];
        if (pp != 0ull && pn != ~0ull) {
            float dp = sqrtf(__uint_as_float((unsigned)(pp >> 32)));
            float dn = sqrtf(__uint_as_float((unsigned)(pn >> 32)));
            acc += fmaxf(dp - dn + 1.0f, 0.f);
            c++;
        }
    }
    #pragma unroll
    for (int o = 16; o; o >>= 1) {
        acc += __shfl_xor_sync(0xffffffffu, acc, o);
        c   += __shfl_xor_sync(0xffffffffu, c, o);
    }
    if ((tid & 31) == 0) { ssum[tid >> 5] = acc; scnt[tid >> 5] = c; }
    __syncthreads();
    if (tid < 32) {
        float a = ssum[tid]; int cc = scnt[tid];
        #pragma unroll
        for (int o = 16; o; o >>= 1) {
            a  += __shfl_xor_sync(0xffffffffu, a, o);
            cc += __shfl_xor_sync(0xffffffffu, cc, o);
        }
        if (!tid) out[0] = a / (float)(cc > 1 ? cc : 1);
    }
}

extern "C" void kernel_launch(void* const* d_in, const int* in_sizes, int n_in,
                              void* d_out, int out_size) {
    const float* emb    = (const float*)d_in[0];
    const int*   labels = (const int*)d_in[1];
    const int*   sbjv   = (const int*)d_in[2];
    float* out = (float*)d_out;

    cudaFuncSetAttribute(mine_k, cudaFuncAttributeMaxDynamicSharedMemorySize, SMEM_DYN);

    k12_k<<<NSUB, 256>>>(sbjv);
    s3_k<<<PTOT / 8, 256>>>(emb, labels);
    mine_k<<<GRID_MINE, 256, SMEM_DYN>>>();
    loss_k<<<1, 1024>>>(out);
}